// round 1
// baseline (speedup 1.0000x reference)
#include <cuda_runtime.h>

#define BSZ   16
#define LSEQ  2048
#define DDIM  256
#define MTOT  (BSZ * LSEQ)   // 32768

#define BM 128
#define BN 128
#define BK 16

// Ping-pong DP state + precomputed 'a'. Static device arrays (no runtime alloc).
__device__ float g_up[2][MTOT * DDIM];
__device__ float g_down[2][MTOT * DDIM];
__device__ float g_a[MTOT * DDIM];

// ---------------------------------------------------------------------------
// prep: a = x @ W1^T + b1  (K=4), and state after DP update #1:
//       up0 = down0 = relu(a + b2)   (since shift(0) @ W2^T == 0)
// ---------------------------------------------------------------------------
__global__ void prep_kernel(const float* __restrict__ x,
                            const float* __restrict__ W1,
                            const float* __restrict__ b1,
                            const float* __restrict__ b2) {
    int idx = blockIdx.x * blockDim.x + threadIdx.x;
    if (idx >= MTOT * DDIM) return;
    int n = idx & (DDIM - 1);
    int m = idx >> 8;                 // DDIM == 256
    int b = m / LSEQ;
    int l = m & (LSEQ - 1);
    const float* xp = x + (size_t)b * 4 * LSEQ + l;
    float s = b1[n];
#pragma unroll
    for (int dd = 0; dd < 4; dd++)
        s = fmaf(xp[dd * LSEQ], W1[n * 4 + dd], s);
    g_a[idx] = s;
    float u0 = fmaxf(s + b2[n], 0.0f);
    g_up[0][idx] = u0;
    g_down[0][idx] = u0;
}

// ---------------------------------------------------------------------------
// One DP iteration, both lanes (blockIdx.z: 0=up shift -1, 1=down shift +1):
//   out[m,n] = relu(a[m,n] + sum_k in[m+shift, k] * W2[n,k] + b2[n])
// with zero input row at the sequence boundary.
// Classic 128x128x16 SGEMM, 256 threads, 8x8 per-thread microtile.
// ---------------------------------------------------------------------------
__global__ __launch_bounds__(256) void dp_iter_kernel(const float* __restrict__ W2,
                                                      const float* __restrict__ b2,
                                                      int src) {
    const int lane = blockIdx.z;
    const float* __restrict__ in  = (lane == 0) ? g_up[src]     : g_down[src];
    float*       __restrict__ out = (lane == 0) ? g_up[src ^ 1] : g_down[src ^ 1];
    const int shift = (lane == 0) ? -1 : 1;

    __shared__ float As[BK][BM];
    __shared__ float Bs[BK][BN];

    const int tid = threadIdx.x;
    const int m0 = blockIdx.x * BM;
    const int n0 = blockIdx.y * BN;

    const int ty = tid >> 4;        // 0..15 (m dir)
    const int tx = tid & 15;        // 0..15 (n dir)

    const int loadRow = tid >> 2;           // 0..63
    const int loadK   = (tid & 3) * 4;      // 0,4,8,12

    float acc[8][8];
#pragma unroll
    for (int i = 0; i < 8; i++)
#pragma unroll
        for (int j = 0; j < 8; j++) acc[i][j] = 0.0f;

    for (int k0 = 0; k0 < DDIM; k0 += BK) {
        // ---- A tile (shifted rows, zero at boundary) ----
#pragma unroll
        for (int r = 0; r < 2; r++) {
            int row  = loadRow + r * 64;
            int mrow = m0 + row;
            int j    = mrow & (LSEQ - 1);
            bool valid = (lane == 0) ? (j > 0) : (j < LSEQ - 1);
            float4 v = make_float4(0.f, 0.f, 0.f, 0.f);
            if (valid) {
                int srcm = mrow + shift;
                v = *reinterpret_cast<const float4*>(in + (size_t)srcm * DDIM + k0 + loadK);
            }
            As[loadK + 0][row] = v.x;
            As[loadK + 1][row] = v.y;
            As[loadK + 2][row] = v.z;
            As[loadK + 3][row] = v.w;
        }
        // ---- B tile: W2[n, k] -> Bs[k][n] ----
#pragma unroll
        for (int r = 0; r < 2; r++) {
            int row  = loadRow + r * 64;
            int nrow = n0 + row;
            float4 v = *reinterpret_cast<const float4*>(W2 + (size_t)nrow * DDIM + k0 + loadK);
            Bs[loadK + 0][row] = v.x;
            Bs[loadK + 1][row] = v.y;
            Bs[loadK + 2][row] = v.z;
            Bs[loadK + 3][row] = v.w;
        }
        __syncthreads();

#pragma unroll
        for (int k = 0; k < BK; k++) {
            float4 a0 = *reinterpret_cast<const float4*>(&As[k][ty * 8]);
            float4 a1 = *reinterpret_cast<const float4*>(&As[k][ty * 8 + 4]);
            float4 c0 = *reinterpret_cast<const float4*>(&Bs[k][tx * 8]);
            float4 c1 = *reinterpret_cast<const float4*>(&Bs[k][tx * 8 + 4]);
            float ar[8] = {a0.x, a0.y, a0.z, a0.w, a1.x, a1.y, a1.z, a1.w};
            float br[8] = {c0.x, c0.y, c0.z, c0.w, c1.x, c1.y, c1.z, c1.w};
#pragma unroll
            for (int i = 0; i < 8; i++)
#pragma unroll
                for (int j = 0; j < 8; j++)
                    acc[i][j] = fmaf(ar[i], br[j], acc[i][j]);
        }
        __syncthreads();
    }

    // ---- epilogue: relu(acc + a + b2) ----
    float bias[8];
#pragma unroll
    for (int j = 0; j < 8; j++) bias[j] = b2[n0 + tx * 8 + j];

#pragma unroll
    for (int i = 0; i < 8; i++) {
        int m = m0 + ty * 8 + i;
        const float* arow = g_a + (size_t)m * DDIM + n0 + tx * 8;
        float*       orow = out + (size_t)m * DDIM + n0 + tx * 8;
        float4 av0 = *reinterpret_cast<const float4*>(arow);
        float4 av1 = *reinterpret_cast<const float4*>(arow + 4);
        float4 o0, o1;
        o0.x = fmaxf(acc[i][0] + av0.x + bias[0], 0.f);
        o0.y = fmaxf(acc[i][1] + av0.y + bias[1], 0.f);
        o0.z = fmaxf(acc[i][2] + av0.z + bias[2], 0.f);
        o0.w = fmaxf(acc[i][3] + av0.w + bias[3], 0.f);
        o1.x = fmaxf(acc[i][4] + av1.x + bias[4], 0.f);
        o1.y = fmaxf(acc[i][5] + av1.y + bias[5], 0.f);
        o1.z = fmaxf(acc[i][6] + av1.z + bias[6], 0.f);
        o1.w = fmaxf(acc[i][7] + av1.w + bias[7], 0.f);
        *reinterpret_cast<float4*>(orow)     = o0;
        *reinterpret_cast<float4*>(orow + 4) = o1;
    }
}

// ---------------------------------------------------------------------------
// final: miu = relu(x@W3^T + b3 + 2*b4 + W4·up[j-1] + W4·down[j+1])
// Same tiling; two accumulation phases (up shift -1, down shift +1) over W4.
// ---------------------------------------------------------------------------
__global__ __launch_bounds__(256) void final_kernel(const float* __restrict__ x,
                                                    const float* __restrict__ W3,
                                                    const float* __restrict__ b3,
                                                    const float* __restrict__ W4,
                                                    const float* __restrict__ b4,
                                                    float* __restrict__ out,
                                                    int src) {
    __shared__ float As[BK][BM];
    __shared__ float Bs[BK][BN];

    const int tid = threadIdx.x;
    const int m0 = blockIdx.x * BM;
    const int n0 = blockIdx.y * BN;
    const int ty = tid >> 4;
    const int tx = tid & 15;
    const int loadRow = tid >> 2;
    const int loadK   = (tid & 3) * 4;

    float acc[8][8];
#pragma unroll
    for (int i = 0; i < 8; i++)
#pragma unroll
        for (int j = 0; j < 8; j++) acc[i][j] = 0.0f;

#pragma unroll
    for (int phase = 0; phase < 2; phase++) {
        const float* __restrict__ in = (phase == 0) ? g_up[src] : g_down[src];
        const int shift = (phase == 0) ? -1 : 1;

        for (int k0 = 0; k0 < DDIM; k0 += BK) {
#pragma unroll
            for (int r = 0; r < 2; r++) {
                int row  = loadRow + r * 64;
                int mrow = m0 + row;
                int j    = mrow & (LSEQ - 1);
                bool valid = (phase == 0) ? (j > 0) : (j < LSEQ - 1);
                float4 v = make_float4(0.f, 0.f, 0.f, 0.f);
                if (valid) {
                    int srcm = mrow + shift;
                    v = *reinterpret_cast<const float4*>(in + (size_t)srcm * DDIM + k0 + loadK);
                }
                As[loadK + 0][row] = v.x;
                As[loadK + 1][row] = v.y;
                As[loadK + 2][row] = v.z;
                As[loadK + 3][row] = v.w;
            }
#pragma unroll
            for (int r = 0; r < 2; r++) {
                int row  = loadRow + r * 64;
                int nrow = n0 + row;
                float4 v = *reinterpret_cast<const float4*>(W4 + (size_t)nrow * DDIM + k0 + loadK);
                Bs[loadK + 0][row] = v.x;
                Bs[loadK + 1][row] = v.y;
                Bs[loadK + 2][row] = v.z;
                Bs[loadK + 3][row] = v.w;
            }
            __syncthreads();

#pragma unroll
            for (int k = 0; k < BK; k++) {
                float4 a0 = *reinterpret_cast<const float4*>(&As[k][ty * 8]);
                float4 a1 = *reinterpret_cast<const float4*>(&As[k][ty * 8 + 4]);
                float4 c0 = *reinterpret_cast<const float4*>(&Bs[k][tx * 8]);
                float4 c1 = *reinterpret_cast<const float4*>(&Bs[k][tx * 8 + 4]);
                float ar[8] = {a0.x, a0.y, a0.z, a0.w, a1.x, a1.y, a1.z, a1.w};
                float br[8] = {c0.x, c0.y, c0.z, c0.w, c1.x, c1.y, c1.z, c1.w};
#pragma unroll
                for (int i = 0; i < 8; i++)
#pragma unroll
                    for (int j = 0; j < 8; j++)
                        acc[i][j] = fmaf(ar[i], br[j], acc[i][j]);
            }
            __syncthreads();
        }
    }

    // epilogue: + x@W3^T + b3 + 2*b4, relu
    float w3r[8][4];
    float bias[8];
#pragma unroll
    for (int j = 0; j < 8; j++) {
        int n = n0 + tx * 8 + j;
        bias[j] = b3[n] + 2.0f * b4[n];
#pragma unroll
        for (int dd = 0; dd < 4; dd++) w3r[j][dd] = W3[n * 4 + dd];
    }

#pragma unroll
    for (int i = 0; i < 8; i++) {
        int m = m0 + ty * 8 + i;
        int b = m / LSEQ;
        int l = m & (LSEQ - 1);
        const float* xp = x + (size_t)b * 4 * LSEQ + l;
        float xv[4];
#pragma unroll
        for (int dd = 0; dd < 4; dd++) xv[dd] = xp[dd * LSEQ];

        float* orow = out + (size_t)m * DDIM + n0 + tx * 8;
        float res[8];
#pragma unroll
        for (int j = 0; j < 8; j++) {
            float s = acc[i][j] + bias[j];
#pragma unroll
            for (int dd = 0; dd < 4; dd++) s = fmaf(xv[dd], w3r[j][dd], s);
            res[j] = fmaxf(s, 0.0f);
        }
        *reinterpret_cast<float4*>(orow)     = make_float4(res[0], res[1], res[2], res[3]);
        *reinterpret_cast<float4*>(orow + 4) = make_float4(res[4], res[5], res[6], res[7]);
    }
}

// ---------------------------------------------------------------------------
extern "C" void kernel_launch(void* const* d_in, const int* in_sizes, int n_in,
                              void* d_out, int out_size) {
    const float* x  = (const float*)d_in[0];
    const float* W1 = (const float*)d_in[1];
    const float* b1 = (const float*)d_in[2];
    const float* W2 = (const float*)d_in[3];
    const float* b2 = (const float*)d_in[4];
    const float* W3 = (const float*)d_in[5];
    const float* b3 = (const float*)d_in[6];
    const float* W4 = (const float*)d_in[7];
    const float* b4 = (const float*)d_in[8];
    float* out = (float*)d_out;

    int total = MTOT * DDIM;
    prep_kernel<<<(total + 255) / 256, 256>>>(x, W1, b1, b2);

    dim3 grid(MTOT / BM, DDIM / BN, 2);
    int src = 0;
    for (int t = 0; t < 7; t++) {          // updates #2..#8 (update #1 done in prep)
        dp_iter_kernel<<<grid, 256>>>(W2, b2, src);
        src ^= 1;
    }
    // after 7 iterations the live state is in buffer (src == 1)
    final_kernel<<<dim3(MTOT / BM, DDIM / BN), 256>>>(x, W3, b3, W4, b4, out, src);
}

// round 3
// speedup vs baseline: 1.8194x; 1.8194x over previous
#include <cuda_runtime.h>
#include <cuda_bf16.h>
#include <cstdint>

#define BSZ   16
#define LSEQ  2048
#define DDIM  256
#define MTOT  (BSZ * LSEQ)   // 32768
#define BM    128
#define BK    32
#define NTHR  512

// ---------------- global state (static, no runtime alloc) ----------------
__device__ float         g_a[MTOT * DDIM];
__device__ __nv_bfloat16 g_up_hi[2][MTOT * DDIM];
__device__ __nv_bfloat16 g_up_lo[2][MTOT * DDIM];
__device__ __nv_bfloat16 g_dn_hi[2][MTOT * DDIM];
__device__ __nv_bfloat16 g_dn_lo[2][MTOT * DDIM];
__device__ __nv_bfloat16 g_W2h[DDIM * DDIM], g_W2l[DDIM * DDIM];
__device__ __nv_bfloat16 g_W4h[DDIM * DDIM], g_W4l[DDIM * DDIM];

// ---------------- helpers ----------------
__device__ __forceinline__ uint32_t smem_u32(const void* p) {
    uint32_t a;
    asm("{ .reg .u64 t; cvta.to.shared.u64 t, %1; cvt.u32.u64 %0, t; }" : "=r"(a) : "l"(p));
    return a;
}
__device__ __forceinline__ void ldm_x4(uint32_t* r, uint32_t addr) {
    asm volatile("ldmatrix.sync.aligned.m8n8.x4.shared.b16 {%0,%1,%2,%3}, [%4];"
                 : "=r"(r[0]), "=r"(r[1]), "=r"(r[2]), "=r"(r[3]) : "r"(addr));
}
__device__ __forceinline__ void mma_bf16(float* c, const uint32_t* a, uint32_t b0, uint32_t b1) {
    asm volatile("mma.sync.aligned.m16n8k16.row.col.f32.bf16.bf16.f32 "
                 "{%0,%1,%2,%3}, {%4,%5,%6,%7}, {%8,%9}, {%0,%1,%2,%3};"
                 : "+f"(c[0]), "+f"(c[1]), "+f"(c[2]), "+f"(c[3])
                 : "r"(a[0]), "r"(a[1]), "r"(a[2]), "r"(a[3]), "r"(b0), "r"(b1));
}
__device__ __forceinline__ void cp16(uint32_t saddr, const void* g, bool valid) {
    int sz = valid ? 16 : 0;
    asm volatile("cp.async.cg.shared.global [%0], [%1], 16, %2;"
                 :: "r"(saddr), "l"(g), "r"(sz) : "memory");
}
#define CP_COMMIT() asm volatile("cp.async.commit_group;" ::: "memory")
#define CP_WAIT0()  asm volatile("cp.async.wait_group 0;" ::: "memory")

// ---------------- SMEM layout ----------------
// Rows padded to 80B (32 bf16 = 64B data + 16B pad) -> conflict-free ldmatrix.
// Stage: A_hi(128x80) A_lo(128x80) B_hi(256x80) B_lo(256x80) = 61440B. x2 stages.
static constexpr int RSTR    = 80;
static constexpr int SA_H    = 0;
static constexpr int SA_L    = SA_H + BM * RSTR;        // 10240
static constexpr int SB_H    = SA_L + BM * RSTR;        // 20480
static constexpr int SB_L    = SB_H + DDIM * RSTR;      // 40960
static constexpr int STAGE   = SB_L + DDIM * RSTR;      // 61440
static constexpr int SMEM_BYTES = 2 * STAGE;            // 122880

// ---------------------------------------------------------------------------
// prep: a = x@W1^T + b1 ; state#1 = relu(a + b2) split to bf16 hi/lo
// ---------------------------------------------------------------------------
__global__ void prep_kernel(const float* __restrict__ x,
                            const float* __restrict__ W1,
                            const float* __restrict__ b1,
                            const float* __restrict__ b2) {
    int idx = blockIdx.x * blockDim.x + threadIdx.x;
    if (idx >= MTOT * DDIM) return;
    int n = idx & (DDIM - 1);
    int m = idx >> 8;
    int b = m / LSEQ;
    int l = m & (LSEQ - 1);
    const float* xp = x + (size_t)b * 4 * LSEQ + l;
    float s = b1[n];
#pragma unroll
    for (int dd = 0; dd < 4; dd++)
        s = fmaf(xp[dd * LSEQ], W1[n * 4 + dd], s);
    g_a[idx] = s;
    float u0 = fmaxf(s + b2[n], 0.0f);
    __nv_bfloat16 h  = __float2bfloat16(u0);
    __nv_bfloat16 lo = __float2bfloat16(u0 - __bfloat162float(h));
    g_up_hi[0][idx] = h;  g_up_lo[0][idx] = lo;
    g_dn_hi[0][idx] = h;  g_dn_lo[0][idx] = lo;
}

__global__ void split_w_kernel(const float* __restrict__ W2,
                               const float* __restrict__ W4) {
    int idx = blockIdx.x * blockDim.x + threadIdx.x;
    if (idx >= DDIM * DDIM) return;
    float w = W2[idx];
    __nv_bfloat16 h = __float2bfloat16(w);
    g_W2h[idx] = h;
    g_W2l[idx] = __float2bfloat16(w - __bfloat162float(h));
    w = W4[idx];
    h = __float2bfloat16(w);
    g_W4h[idx] = h;
    g_W4l[idx] = __float2bfloat16(w - __bfloat162float(h));
}

// ---------------------------------------------------------------------------
// stage loader: A = shifted state rows [m0,m0+128) x k[k0,k0+32), B = weights
// ---------------------------------------------------------------------------
__device__ __forceinline__ void issue_stage(uint32_t sbase, int tid,
                                            const __nv_bfloat16* __restrict__ inh,
                                            const __nv_bfloat16* __restrict__ inl,
                                            const __nv_bfloat16* __restrict__ wh,
                                            const __nv_bfloat16* __restrict__ wl,
                                            int m0, int shift, int k0) {
    // A: 128 rows x 4 segs (16B). One (r,seg) per thread.
    {
        int r = tid >> 2, seg = tid & 3;
        int mrow = m0 + r;
        int j = mrow & (LSEQ - 1);
        bool valid = (shift < 0) ? (j > 0) : (j < LSEQ - 1);
        int grow = valid ? (mrow + shift) : mrow;   // clamped addr when invalid
        size_t goff = (size_t)grow * DDIM + k0 + seg * 8;
        uint32_t so = (uint32_t)(r * RSTR + seg * 16);
        cp16(sbase + SA_H + so, inh + goff, valid);
        cp16(sbase + SA_L + so, inl + goff, valid);
    }
    // B: 256 rows x 4 segs. Two (r,seg) per thread.
#pragma unroll
    for (int u = tid; u < 1024; u += NTHR) {
        int r = u >> 2, seg = u & 3;
        size_t goff = (size_t)r * DDIM + k0 + seg * 8;
        uint32_t so = (uint32_t)(r * RSTR + seg * 16);
        cp16(sbase + SB_H + so, wh + goff, true);
        cp16(sbase + SB_L + so, wl + goff, true);
    }
}

// compute one BK=32 stage into acc[2][8][4] (3-pass bf16x3)
__device__ __forceinline__ void compute_stage(uint32_t base, int lane, int wm, int wn,
                                              float acc[2][8][4]) {
#pragma unroll
    for (int ks = 0; ks < 2; ks++) {
        uint32_t cb = ks * 32 + ((lane >> 4) * 16);
        uint32_t rlo = (uint32_t)(lane & 15);
        uint32_t ah[2][4], al[2][4];
#pragma unroll
        for (int mt = 0; mt < 2; mt++) {
            uint32_t row = wm * 32 + mt * 16 + rlo;
            ldm_x4(ah[mt], base + SA_H + row * RSTR + cb);
            ldm_x4(al[mt], base + SA_L + row * RSTR + cb);
        }
#pragma unroll
        for (int pr = 0; pr < 4; pr++) {
            uint32_t brow = wn * 64 + pr * 16 + rlo;
            uint32_t bh[4], bl[4];
            ldm_x4(bh, base + SB_H + brow * RSTR + cb);
            ldm_x4(bl, base + SB_L + brow * RSTR + cb);
#pragma unroll
            for (int mt = 0; mt < 2; mt++) {
                mma_bf16(acc[mt][pr * 2],     ah[mt], bh[0], bh[2]);
                mma_bf16(acc[mt][pr * 2 + 1], ah[mt], bh[1], bh[3]);
                mma_bf16(acc[mt][pr * 2],     ah[mt], bl[0], bl[2]);
                mma_bf16(acc[mt][pr * 2 + 1], ah[mt], bl[1], bl[3]);
                mma_bf16(acc[mt][pr * 2],     al[mt], bh[0], bh[2]);
                mma_bf16(acc[mt][pr * 2 + 1], al[mt], bh[1], bh[3]);
            }
        }
    }
}

// ---------------------------------------------------------------------------
// DP iteration: out = relu(a + shift(in)@W2^T + b2). blockIdx.y = lane.
// ---------------------------------------------------------------------------
__global__ __launch_bounds__(NTHR, 1) void dp_iter_kernel(const float* __restrict__ b2,
                                                          int src) {
    extern __shared__ char smem[];
    const uint32_t sb = smem_u32(smem);
    const int tid = threadIdx.x, lane = tid & 31, wid = tid >> 5;
    const int wm = wid >> 2, wn = wid & 3;
    const int m0 = blockIdx.x * BM;
    const int ln = blockIdx.y;

    const __nv_bfloat16* inh = ln ? g_dn_hi[src] : g_up_hi[src];
    const __nv_bfloat16* inl = ln ? g_dn_lo[src] : g_up_lo[src];
    __nv_bfloat16* outh = ln ? g_dn_hi[src ^ 1] : g_up_hi[src ^ 1];
    __nv_bfloat16* outl = ln ? g_dn_lo[src ^ 1] : g_up_lo[src ^ 1];
    const int shift = ln ? 1 : -1;

    float acc[2][8][4];
#pragma unroll
    for (int i = 0; i < 2; i++)
#pragma unroll
        for (int j = 0; j < 8; j++)
#pragma unroll
            for (int q = 0; q < 4; q++) acc[i][j][q] = 0.0f;

    issue_stage(sb, tid, inh, inl, g_W2h, g_W2l, m0, shift, 0);
    CP_COMMIT();
#pragma unroll 1
    for (int c = 0; c < 8; c++) {
        CP_WAIT0();
        __syncthreads();
        if (c < 7) {
            issue_stage(sb + ((c + 1) & 1) * STAGE, tid, inh, inl, g_W2h, g_W2l,
                        m0, shift, (c + 1) * BK);
            CP_COMMIT();
        }
        compute_stage(sb + (c & 1) * STAGE, lane, wm, wn, acc);
    }

    // epilogue: relu(acc + a + b2) -> bf16 hi/lo
#pragma unroll
    for (int mt = 0; mt < 2; mt++) {
#pragma unroll
        for (int nt = 0; nt < 8; nt++) {
            int n = wn * 64 + nt * 8 + (lane & 3) * 2;
            float2 bv = *reinterpret_cast<const float2*>(b2 + n);
#pragma unroll
            for (int h = 0; h < 2; h++) {
                int m = m0 + wm * 32 + mt * 16 + (lane >> 2) + h * 8;
                float2 av = *reinterpret_cast<const float2*>(g_a + (size_t)m * DDIM + n);
                float v0 = fmaxf(acc[mt][nt][2 * h]     + av.x + bv.x, 0.0f);
                float v1 = fmaxf(acc[mt][nt][2 * h + 1] + av.y + bv.y, 0.0f);
                __nv_bfloat162 hv, lv;
                hv.x = __float2bfloat16(v0);
                hv.y = __float2bfloat16(v1);
                lv.x = __float2bfloat16(v0 - __bfloat162float(hv.x));
                lv.y = __float2bfloat16(v1 - __bfloat162float(hv.y));
                *reinterpret_cast<__nv_bfloat162*>(outh + (size_t)m * DDIM + n) = hv;
                *reinterpret_cast<__nv_bfloat162*>(outl + (size_t)m * DDIM + n) = lv;
            }
        }
    }
}

// ---------------------------------------------------------------------------
// final: miu = relu(x@W3^T + b3 + 2*b4 + W4*up[j-1] + W4*down[j+1])
// 16 stages: t<8 -> up phase (shift -1), t>=8 -> down phase (shift +1).
// ---------------------------------------------------------------------------
__global__ __launch_bounds__(NTHR, 1) void final_kernel(const float* __restrict__ x,
                                                        const float* __restrict__ W3,
                                                        const float* __restrict__ b3,
                                                        const float* __restrict__ b4,
                                                        float* __restrict__ out,
                                                        int src) {
    extern __shared__ char smem[];
    const uint32_t sb = smem_u32(smem);
    const int tid = threadIdx.x, lane = tid & 31, wid = tid >> 5;
    const int wm = wid >> 2, wn = wid & 3;
    const int m0 = blockIdx.x * BM;

    float acc[2][8][4];
#pragma unroll
    for (int i = 0; i < 2; i++)
#pragma unroll
        for (int j = 0; j < 8; j++)
#pragma unroll
            for (int q = 0; q < 4; q++) acc[i][j][q] = 0.0f;

    issue_stage(sb, tid, g_up_hi[src], g_up_lo[src], g_W4h, g_W4l, m0, -1, 0);
    CP_COMMIT();
#pragma unroll 1
    for (int t = 0; t < 16; t++) {
        CP_WAIT0();
        __syncthreads();
        if (t < 15) {
            int tn = t + 1;
            int ph = tn >> 3;
            const __nv_bfloat16* inh = ph ? g_dn_hi[src] : g_up_hi[src];
            const __nv_bfloat16* inl = ph ? g_dn_lo[src] : g_up_lo[src];
            issue_stage(sb + (tn & 1) * STAGE, tid, inh, inl, g_W4h, g_W4l,
                        m0, ph ? 1 : -1, (tn & 7) * BK);
            CP_COMMIT();
        }
        compute_stage(sb + (t & 1) * STAGE, lane, wm, wn, acc);
    }

    // epilogue: + x@W3^T + b3 + 2*b4, relu, fp32 out
#pragma unroll
    for (int mt = 0; mt < 2; mt++) {
#pragma unroll
        for (int h = 0; h < 2; h++) {
            int m = m0 + wm * 32 + mt * 16 + (lane >> 2) + h * 8;
            int b = m >> 11;
            int l = m & (LSEQ - 1);
            const float* xp = x + (size_t)b * 4 * LSEQ + l;
            float xv[4];
#pragma unroll
            for (int dd = 0; dd < 4; dd++) xv[dd] = xp[dd * LSEQ];
            float* orow = out + (size_t)m * DDIM;
#pragma unroll
            for (int nt = 0; nt < 8; nt++) {
                int n = wn * 64 + nt * 8 + (lane & 3) * 2;
                float2 b3v = *reinterpret_cast<const float2*>(b3 + n);
                float2 b4v = *reinterpret_cast<const float2*>(b4 + n);
                float v0 = acc[mt][nt][2 * h]     + b3v.x + 2.0f * b4v.x;
                float v1 = acc[mt][nt][2 * h + 1] + b3v.y + 2.0f * b4v.y;
#pragma unroll
                for (int dd = 0; dd < 4; dd++) {
                    v0 = fmaf(xv[dd], W3[n * 4 + dd],     v0);
                    v1 = fmaf(xv[dd], W3[(n + 1) * 4 + dd], v1);
                }
                float2 o = make_float2(fmaxf(v0, 0.0f), fmaxf(v1, 0.0f));
                *reinterpret_cast<float2*>(orow + n) = o;
            }
        }
    }
}

// ---------------------------------------------------------------------------
extern "C" void kernel_launch(void* const* d_in, const int* in_sizes, int n_in,
                              void* d_out, int out_size) {
    const float* x  = (const float*)d_in[0];
    const float* W1 = (const float*)d_in[1];
    const float* b1 = (const float*)d_in[2];
    const float* W2 = (const float*)d_in[3];
    const float* b2 = (const float*)d_in[4];
    const float* W3 = (const float*)d_in[5];
    const float* b3 = (const float*)d_in[6];
    const float* W4 = (const float*)d_in[7];
    const float* b4 = (const float*)d_in[8];
    float* out = (float*)d_out;

    cudaFuncSetAttribute(dp_iter_kernel, cudaFuncAttributeMaxDynamicSharedMemorySize, SMEM_BYTES);
    cudaFuncSetAttribute(final_kernel,   cudaFuncAttributeMaxDynamicSharedMemorySize, SMEM_BYTES);

    int total = MTOT * DDIM;
    prep_kernel<<<(total + 255) / 256, 256>>>(x, W1, b1, b2);
    split_w_kernel<<<(DDIM * DDIM + 255) / 256, 256>>>(W2, W4);

    int src = 0;
    for (int t = 0; t < 7; t++) {
        dp_iter_kernel<<<dim3(MTOT / BM, 2), NTHR, SMEM_BYTES>>>(b2, src);
        src ^= 1;
    }
    final_kernel<<<MTOT / BM, NTHR, SMEM_BYTES>>>(x, W3, b3, b4, out, src);
}

// round 4
// speedup vs baseline: 2.1970x; 1.2075x over previous
#include <cuda_runtime.h>
#include <cuda_bf16.h>
#include <cstdint>

#define BSZ   16
#define LSEQ  2048
#define DDIM  256
#define MTOT  (BSZ * LSEQ)   // 32768
#define BM    128
#define BN    128
#define BK    32
#define NTHR  256

// ---------------- global state (static, no runtime alloc) ----------------
__device__ float         g_a[MTOT * DDIM];
__device__ __nv_bfloat16 g_up_hi[2][MTOT * DDIM];
__device__ __nv_bfloat16 g_up_lo[2][MTOT * DDIM];
__device__ __nv_bfloat16 g_dn_hi[2][MTOT * DDIM];
__device__ __nv_bfloat16 g_dn_lo[2][MTOT * DDIM];
__device__ __nv_bfloat16 g_W2h[DDIM * DDIM], g_W2l[DDIM * DDIM];
__device__ __nv_bfloat16 g_W4h[DDIM * DDIM], g_W4l[DDIM * DDIM];

// ---------------- helpers ----------------
__device__ __forceinline__ uint32_t smem_u32(const void* p) {
    uint32_t a;
    asm("{ .reg .u64 t; cvta.to.shared.u64 t, %1; cvt.u32.u64 %0, t; }" : "=r"(a) : "l"(p));
    return a;
}
__device__ __forceinline__ void ldm_x4(uint32_t* r, uint32_t addr) {
    asm volatile("ldmatrix.sync.aligned.m8n8.x4.shared.b16 {%0,%1,%2,%3}, [%4];"
                 : "=r"(r[0]), "=r"(r[1]), "=r"(r[2]), "=r"(r[3]) : "r"(addr));
}
__device__ __forceinline__ void mma_bf16(float* c, const uint32_t* a, uint32_t b0, uint32_t b1) {
    asm volatile("mma.sync.aligned.m16n8k16.row.col.f32.bf16.bf16.f32 "
                 "{%0,%1,%2,%3}, {%4,%5,%6,%7}, {%8,%9}, {%0,%1,%2,%3};"
                 : "+f"(c[0]), "+f"(c[1]), "+f"(c[2]), "+f"(c[3])
                 : "r"(a[0]), "r"(a[1]), "r"(a[2]), "r"(a[3]), "r"(b0), "r"(b1));
}
__device__ __forceinline__ void cp16(uint32_t saddr, const void* g, bool valid) {
    int sz = valid ? 16 : 0;
    asm volatile("cp.async.cg.shared.global [%0], [%1], 16, %2;"
                 :: "r"(saddr), "l"(g), "r"(sz) : "memory");
}
#define CP_COMMIT() asm volatile("cp.async.commit_group;" ::: "memory")
#define CP_WAIT0()  asm volatile("cp.async.wait_group 0;" ::: "memory")

// ---------------- SMEM layout ----------------
// Rows padded to 80B (32 bf16 = 64B data + 16B pad) -> conflict-free ldmatrix.
// Stage: A_hi(128x80) A_lo B_hi(128x80) B_lo = 40960B. x2 stages = 80KB
// -> 2 CTAs/SM (160KB of 228KB).
static constexpr int RSTR    = 80;
static constexpr int SA_H    = 0;
static constexpr int SA_L    = SA_H + BM * RSTR;        // 10240
static constexpr int SB_H    = SA_L + BM * RSTR;        // 20480
static constexpr int SB_L    = SB_H + BN * RSTR;        // 30720
static constexpr int STAGE   = SB_L + BN * RSTR;        // 40960
static constexpr int SMEM_BYTES = 2 * STAGE;            // 81920

// ---------------------------------------------------------------------------
// prep: a = x@W1^T + b1 ; state#1 = relu(a + b2) split to bf16 hi/lo
// ---------------------------------------------------------------------------
__global__ void prep_kernel(const float* __restrict__ x,
                            const float* __restrict__ W1,
                            const float* __restrict__ b1,
                            const float* __restrict__ b2) {
    int idx = blockIdx.x * blockDim.x + threadIdx.x;
    if (idx >= MTOT * DDIM) return;
    int n = idx & (DDIM - 1);
    int m = idx >> 8;
    int b = m / LSEQ;
    int l = m & (LSEQ - 1);
    const float* xp = x + (size_t)b * 4 * LSEQ + l;
    float s = b1[n];
#pragma unroll
    for (int dd = 0; dd < 4; dd++)
        s = fmaf(xp[dd * LSEQ], W1[n * 4 + dd], s);
    g_a[idx] = s;
    float u0 = fmaxf(s + b2[n], 0.0f);
    __nv_bfloat16 h  = __float2bfloat16(u0);
    __nv_bfloat16 lo = __float2bfloat16(u0 - __bfloat162float(h));
    g_up_hi[0][idx] = h;  g_up_lo[0][idx] = lo;
    g_dn_hi[0][idx] = h;  g_dn_lo[0][idx] = lo;
}

__global__ void split_w_kernel(const float* __restrict__ W2,
                               const float* __restrict__ W4) {
    int idx = blockIdx.x * blockDim.x + threadIdx.x;
    if (idx >= DDIM * DDIM) return;
    float w = W2[idx];
    __nv_bfloat16 h = __float2bfloat16(w);
    g_W2h[idx] = h;
    g_W2l[idx] = __float2bfloat16(w - __bfloat162float(h));
    w = W4[idx];
    h = __float2bfloat16(w);
    g_W4h[idx] = h;
    g_W4l[idx] = __float2bfloat16(w - __bfloat162float(h));
}

// ---------------------------------------------------------------------------
// stage loader: A = shifted state rows [m0,m0+128) x k[k0,k0+32),
//               B = weight rows [n0,n0+128) x k[k0,k0+32)
// 256 threads, 2 (r,seg) pairs each per tile.
// ---------------------------------------------------------------------------
__device__ __forceinline__ void issue_stage(uint32_t sbase, int tid,
                                            const __nv_bfloat16* __restrict__ inh,
                                            const __nv_bfloat16* __restrict__ inl,
                                            const __nv_bfloat16* __restrict__ wh,
                                            const __nv_bfloat16* __restrict__ wl,
                                            int m0, int n0, int shift, int k0) {
#pragma unroll
    for (int u = tid; u < 512; u += NTHR) {
        int r = u >> 2, seg = u & 3;
        int mrow = m0 + r;
        int j = mrow & (LSEQ - 1);
        bool valid = (shift < 0) ? (j > 0) : (j < LSEQ - 1);
        int grow = valid ? (mrow + shift) : mrow;
        size_t goff = (size_t)grow * DDIM + k0 + seg * 8;
        uint32_t so = (uint32_t)(r * RSTR + seg * 16);
        cp16(sbase + SA_H + so, inh + goff, valid);
        cp16(sbase + SA_L + so, inl + goff, valid);
    }
#pragma unroll
    for (int u = tid; u < 512; u += NTHR) {
        int r = u >> 2, seg = u & 3;
        size_t goff = (size_t)(n0 + r) * DDIM + k0 + seg * 8;
        uint32_t so = (uint32_t)(r * RSTR + seg * 16);
        cp16(sbase + SB_H + so, wh + goff, true);
        cp16(sbase + SB_L + so, wl + goff, true);
    }
}

// compute one BK=32 stage into acc[2][8][4] (3-pass bf16x3). warp tile 32x64.
__device__ __forceinline__ void compute_stage(uint32_t base, int lane, int wm, int wn,
                                              float acc[2][8][4]) {
#pragma unroll
    for (int ks = 0; ks < 2; ks++) {
        uint32_t cb = ks * 32 + ((lane >> 4) * 16);
        uint32_t rlo = (uint32_t)(lane & 15);
        uint32_t ah[2][4], al[2][4];
#pragma unroll
        for (int mt = 0; mt < 2; mt++) {
            uint32_t row = wm * 32 + mt * 16 + rlo;
            ldm_x4(ah[mt], base + SA_H + row * RSTR + cb);
            ldm_x4(al[mt], base + SA_L + row * RSTR + cb);
        }
#pragma unroll
        for (int pr = 0; pr < 4; pr++) {
            uint32_t brow = wn * 64 + pr * 16 + rlo;
            uint32_t bh[4], bl[4];
            ldm_x4(bh, base + SB_H + brow * RSTR + cb);
            ldm_x4(bl, base + SB_L + brow * RSTR + cb);
#pragma unroll
            for (int mt = 0; mt < 2; mt++) {
                mma_bf16(acc[mt][pr * 2],     ah[mt], bh[0], bh[2]);
                mma_bf16(acc[mt][pr * 2 + 1], ah[mt], bh[1], bh[3]);
                mma_bf16(acc[mt][pr * 2],     ah[mt], bl[0], bl[2]);
                mma_bf16(acc[mt][pr * 2 + 1], ah[mt], bl[1], bl[3]);
                mma_bf16(acc[mt][pr * 2],     al[mt], bh[0], bh[2]);
                mma_bf16(acc[mt][pr * 2 + 1], al[mt], bh[1], bh[3]);
            }
        }
    }
}

// ---------------------------------------------------------------------------
// DP iteration: out = relu(a + shift(in)@W2^T + b2).
// grid = (m_tiles, n_halves=2, lanes=2). 256 thr, 8 warps = 4m x 2n.
// ---------------------------------------------------------------------------
__global__ __launch_bounds__(NTHR, 2) void dp_iter_kernel(const float* __restrict__ b2,
                                                          int src) {
    extern __shared__ char smem[];
    const uint32_t sb = smem_u32(smem);
    const int tid = threadIdx.x, lane = tid & 31, wid = tid >> 5;
    const int wm = wid >> 1, wn = wid & 1;
    const int m0 = blockIdx.x * BM;
    const int n0 = blockIdx.y * BN;
    const int ln = blockIdx.z;

    const __nv_bfloat16* inh = ln ? g_dn_hi[src] : g_up_hi[src];
    const __nv_bfloat16* inl = ln ? g_dn_lo[src] : g_up_lo[src];
    __nv_bfloat16* outh = ln ? g_dn_hi[src ^ 1] : g_up_hi[src ^ 1];
    __nv_bfloat16* outl = ln ? g_dn_lo[src ^ 1] : g_up_lo[src ^ 1];
    const int shift = ln ? 1 : -1;

    float acc[2][8][4];
#pragma unroll
    for (int i = 0; i < 2; i++)
#pragma unroll
        for (int j = 0; j < 8; j++)
#pragma unroll
            for (int q = 0; q < 4; q++) acc[i][j][q] = 0.0f;

    issue_stage(sb, tid, inh, inl, g_W2h, g_W2l, m0, n0, shift, 0);
    CP_COMMIT();
#pragma unroll 1
    for (int c = 0; c < 8; c++) {
        CP_WAIT0();
        __syncthreads();
        if (c < 7) {
            issue_stage(sb + ((c + 1) & 1) * STAGE, tid, inh, inl, g_W2h, g_W2l,
                        m0, n0, shift, (c + 1) * BK);
            CP_COMMIT();
        }
        compute_stage(sb + (c & 1) * STAGE, lane, wm, wn, acc);
    }

    // epilogue: relu(acc + a + b2) -> bf16 hi/lo
#pragma unroll
    for (int mt = 0; mt < 2; mt++) {
#pragma unroll
        for (int nt = 0; nt < 8; nt++) {
            int n = n0 + wn * 64 + nt * 8 + (lane & 3) * 2;
            float2 bv = *reinterpret_cast<const float2*>(b2 + n);
#pragma unroll
            for (int h = 0; h < 2; h++) {
                int m = m0 + wm * 32 + mt * 16 + (lane >> 2) + h * 8;
                float2 av = *reinterpret_cast<const float2*>(g_a + (size_t)m * DDIM + n);
                float v0 = fmaxf(acc[mt][nt][2 * h]     + av.x + bv.x, 0.0f);
                float v1 = fmaxf(acc[mt][nt][2 * h + 1] + av.y + bv.y, 0.0f);
                __nv_bfloat162 hv, lv;
                hv.x = __float2bfloat16(v0);
                hv.y = __float2bfloat16(v1);
                lv.x = __float2bfloat16(v0 - __bfloat162float(hv.x));
                lv.y = __float2bfloat16(v1 - __bfloat162float(hv.y));
                *reinterpret_cast<__nv_bfloat162*>(outh + (size_t)m * DDIM + n) = hv;
                *reinterpret_cast<__nv_bfloat162*>(outl + (size_t)m * DDIM + n) = lv;
            }
        }
    }
}

// ---------------------------------------------------------------------------
// final: miu = relu(x@W3^T + b3 + 2*b4 + W4*up[j-1] + W4*down[j+1])
// 16 stages: t<8 -> up (shift -1), t>=8 -> down (shift +1). grid = (m, 2).
// ---------------------------------------------------------------------------
__global__ __launch_bounds__(NTHR, 2) void final_kernel(const float* __restrict__ x,
                                                        const float* __restrict__ W3,
                                                        const float* __restrict__ b3,
                                                        const float* __restrict__ b4,
                                                        float* __restrict__ out,
                                                        int src) {
    extern __shared__ char smem[];
    const uint32_t sb = smem_u32(smem);
    const int tid = threadIdx.x, lane = tid & 31, wid = tid >> 5;
    const int wm = wid >> 1, wn = wid & 1;
    const int m0 = blockIdx.x * BM;
    const int n0 = blockIdx.y * BN;

    float acc[2][8][4];
#pragma unroll
    for (int i = 0; i < 2; i++)
#pragma unroll
        for (int j = 0; j < 8; j++)
#pragma unroll
            for (int q = 0; q < 4; q++) acc[i][j][q] = 0.0f;

    issue_stage(sb, tid, g_up_hi[src], g_up_lo[src], g_W4h, g_W4l, m0, n0, -1, 0);
    CP_COMMIT();
#pragma unroll 1
    for (int t = 0; t < 16; t++) {
        CP_WAIT0();
        __syncthreads();
        if (t < 15) {
            int tn = t + 1;
            int ph = tn >> 3;
            const __nv_bfloat16* inh = ph ? g_dn_hi[src] : g_up_hi[src];
            const __nv_bfloat16* inl = ph ? g_dn_lo[src] : g_up_lo[src];
            issue_stage(sb + (tn & 1) * STAGE, tid, inh, inl, g_W4h, g_W4l,
                        m0, n0, ph ? 1 : -1, (tn & 7) * BK);
            CP_COMMIT();
        }
        compute_stage(sb + (t & 1) * STAGE, lane, wm, wn, acc);
    }

    // epilogue: + x@W3^T + b3 + 2*b4, relu, fp32 out
#pragma unroll
    for (int mt = 0; mt < 2; mt++) {
#pragma unroll
        for (int h = 0; h < 2; h++) {
            int m = m0 + wm * 32 + mt * 16 + (lane >> 2) + h * 8;
            int b = m >> 11;
            int l = m & (LSEQ - 1);
            const float* xp = x + (size_t)b * 4 * LSEQ + l;
            float xv[4];
#pragma unroll
            for (int dd = 0; dd < 4; dd++) xv[dd] = xp[dd * LSEQ];
            float* orow = out + (size_t)m * DDIM;
#pragma unroll
            for (int nt = 0; nt < 8; nt++) {
                int n = n0 + wn * 64 + nt * 8 + (lane & 3) * 2;
                float2 b3v = *reinterpret_cast<const float2*>(b3 + n);
                float2 b4v = *reinterpret_cast<const float2*>(b4 + n);
                float v0 = acc[mt][nt][2 * h]     + b3v.x + 2.0f * b4v.x;
                float v1 = acc[mt][nt][2 * h + 1] + b3v.y + 2.0f * b4v.y;
#pragma unroll
                for (int dd = 0; dd < 4; dd++) {
                    v0 = fmaf(xv[dd], W3[n * 4 + dd],       v0);
                    v1 = fmaf(xv[dd], W3[(n + 1) * 4 + dd], v1);
                }
                float2 o = make_float2(fmaxf(v0, 0.0f), fmaxf(v1, 0.0f));
                *reinterpret_cast<float2*>(orow + n) = o;
            }
        }
    }
}

// ---------------------------------------------------------------------------
extern "C" void kernel_launch(void* const* d_in, const int* in_sizes, int n_in,
                              void* d_out, int out_size) {
    const float* x  = (const float*)d_in[0];
    const float* W1 = (const float*)d_in[1];
    const float* b1 = (const float*)d_in[2];
    const float* W2 = (const float*)d_in[3];
    const float* b2 = (const float*)d_in[4];
    const float* W3 = (const float*)d_in[5];
    const float* b3 = (const float*)d_in[6];
    const float* W4 = (const float*)d_in[7];
    const float* b4 = (const float*)d_in[8];
    float* out = (float*)d_out;

    cudaFuncSetAttribute(dp_iter_kernel, cudaFuncAttributeMaxDynamicSharedMemorySize, SMEM_BYTES);
    cudaFuncSetAttribute(final_kernel,   cudaFuncAttributeMaxDynamicSharedMemorySize, SMEM_BYTES);

    int total = MTOT * DDIM;
    prep_kernel<<<(total + 255) / 256, 256>>>(x, W1, b1, b2);
    split_w_kernel<<<(DDIM * DDIM + 255) / 256, 256>>>(W2, W4);

    int src = 0;
    for (int t = 0; t < 7; t++) {
        dp_iter_kernel<<<dim3(MTOT / BM, 2, 2), NTHR, SMEM_BYTES>>>(b2, src);
        src ^= 1;
    }
    final_kernel<<<dim3(MTOT / BM, 2), NTHR, SMEM_BYTES>>>(x, W3, b3, b4, out, src);
}

// round 5
// speedup vs baseline: 2.4593x; 1.1193x over previous
#include <cuda_runtime.h>
#include <cuda_bf16.h>
#include <cstdint>

#define BSZ   16
#define LSEQ  2048
#define DDIM  256
#define MTOT  (BSZ * LSEQ)    // 32768
#define BM    128
#define BN    128
#define NTHR  256

// padded chunk-major state layout:
// chunk c (32 k-values), row = b*(LSEQ+2) + l + 1, 40 bf16 per row (64B data + 16B pad)
#define CHUNKS 8
#define CHROW  (LSEQ + 2)                 // 2050 rows per sequence (pad front/back)
#define RELEM  40                         // bf16 per padded row (80 bytes)
#define ROWS_PER_CHUNK (BSZ * CHROW)      // 32800
#define CH_ELEMS ((size_t)ROWS_PER_CHUNK * RELEM)
#define W_CH   (256 * RELEM)              // weight chunk: 256 rows x 40 elems

// ---------------- global state (static .bss, zero-init; pads stay zero) ----
__device__ float         g_a[MTOT * DDIM];
__device__ __nv_bfloat16 g_up_hi[2][CHUNKS * CH_ELEMS];
__device__ __nv_bfloat16 g_up_lo[2][CHUNKS * CH_ELEMS];
__device__ __nv_bfloat16 g_dn_hi[2][CHUNKS * CH_ELEMS];
__device__ __nv_bfloat16 g_dn_lo[2][CHUNKS * CH_ELEMS];
__device__ __nv_bfloat16 g_W2h[CHUNKS * W_CH], g_W2l[CHUNKS * W_CH];
__device__ __nv_bfloat16 g_W4h[CHUNKS * W_CH], g_W4l[CHUNKS * W_CH];

// ---------------- helpers ----------------
__device__ __forceinline__ uint32_t smem_u32(const void* p) {
    uint32_t a;
    asm("{ .reg .u64 t; cvta.to.shared.u64 t, %1; cvt.u32.u64 %0, t; }" : "=r"(a) : "l"(p));
    return a;
}
__device__ __forceinline__ void ldm_x4(uint32_t* r, uint32_t addr) {
    asm volatile("ldmatrix.sync.aligned.m8n8.x4.shared.b16 {%0,%1,%2,%3}, [%4];"
                 : "=r"(r[0]), "=r"(r[1]), "=r"(r[2]), "=r"(r[3]) : "r"(addr));
}
__device__ __forceinline__ void mma_bf16(float* c, const uint32_t* a, uint32_t b0, uint32_t b1) {
    asm volatile("mma.sync.aligned.m16n8k16.row.col.f32.bf16.bf16.f32 "
                 "{%0,%1,%2,%3}, {%4,%5,%6,%7}, {%8,%9}, {%0,%1,%2,%3};"
                 : "+f"(c[0]), "+f"(c[1]), "+f"(c[2]), "+f"(c[3])
                 : "r"(a[0]), "r"(a[1]), "r"(a[2]), "r"(a[3]), "r"(b0), "r"(b1));
}
__device__ __forceinline__ void bulk_g2s(uint32_t sdst, const void* gsrc,
                                         uint32_t bytes, uint32_t mbar) {
    asm volatile(
        "cp.async.bulk.shared::cluster.global.mbarrier::complete_tx::bytes [%0], [%1], %2, [%3];"
        :: "r"(sdst), "l"(gsrc), "r"(bytes), "r"(mbar) : "memory");
}
__device__ __forceinline__ void mbar_init(uint32_t mbar, uint32_t cnt) {
    asm volatile("mbarrier.init.shared.b64 [%0], %1;" :: "r"(mbar), "r"(cnt) : "memory");
}
__device__ __forceinline__ void mbar_expect_tx(uint32_t mbar, uint32_t bytes) {
    asm volatile("mbarrier.arrive.expect_tx.shared.b64 _, [%0], %1;"
                 :: "r"(mbar), "r"(bytes) : "memory");
}
__device__ __forceinline__ void mbar_wait(uint32_t mbar, uint32_t parity) {
    uint32_t done;
    asm volatile(
        "{\n\t.reg .pred p;\n\t"
        "mbarrier.try_wait.parity.acquire.cta.shared::cta.b64 p, [%1], %2;\n\t"
        "selp.b32 %0, 1, 0, p;\n\t}"
        : "=r"(done) : "r"(mbar), "r"(parity) : "memory");
    if (!done) {
        asm volatile(
            "{\n\t.reg .pred P1;\n\t"
            "W_%=:\n\t"
            "mbarrier.try_wait.parity.acquire.cta.shared::cta.b64 P1, [%0], %1, 0x989680;\n\t"
            "@P1 bra.uni D_%=;\n\t"
            "bra.uni W_%=;\n\t"
            "D_%=:\n\t}"
            :: "r"(mbar), "r"(parity) : "memory");
    }
}

// ---------------- SMEM layout ----------------
static constexpr int RSTR  = 80;
static constexpr int SA_H  = 0;
static constexpr int SA_L  = SA_H + BM * RSTR;        // 10240
static constexpr int SB_H  = SA_L + BM * RSTR;        // 20480
static constexpr int SB_L  = SB_H + BN * RSTR;        // 30720
static constexpr int STAGE = SB_L + BN * RSTR;        // 40960
static constexpr int SM_MBAR = 2 * STAGE;             // 81920
static constexpr int SMEM_BYTES = SM_MBAR + 32;       // 81952
static constexpr uint32_t TILE_BYTES = BM * RSTR;     // 10240 per bulk

// state element offset for (m, n)
__device__ __forceinline__ size_t st_off(int m, int n) {
    int chunk = n >> 5;
    int row = (m >> 11) * CHROW + (m & (LSEQ - 1)) + 1;
    return (size_t)chunk * CH_ELEMS + (size_t)row * RELEM + (n & 31);
}

// ---------------------------------------------------------------------------
// prep: a = x@W1^T + b1 ; state#1 = relu(a + b2) split into padded layout
// ---------------------------------------------------------------------------
__global__ void prep_kernel(const float* __restrict__ x,
                            const float* __restrict__ W1,
                            const float* __restrict__ b1,
                            const float* __restrict__ b2) {
    int idx = blockIdx.x * blockDim.x + threadIdx.x;
    if (idx >= MTOT * DDIM) return;
    int n = idx & (DDIM - 1);
    int m = idx >> 8;
    int b = m / LSEQ;
    int l = m & (LSEQ - 1);
    const float* xp = x + (size_t)b * 4 * LSEQ + l;
    float s = b1[n];
#pragma unroll
    for (int dd = 0; dd < 4; dd++)
        s = fmaf(xp[dd * LSEQ], W1[n * 4 + dd], s);
    g_a[idx] = s;
    float u0 = fmaxf(s + b2[n], 0.0f);
    __nv_bfloat16 h  = __float2bfloat16(u0);
    __nv_bfloat16 lo = __float2bfloat16(u0 - __bfloat162float(h));
    size_t off = st_off(m, n);
    g_up_hi[0][off] = h;  g_up_lo[0][off] = lo;
    g_dn_hi[0][off] = h;  g_dn_lo[0][off] = lo;
}

// split W2/W4 hi/lo into chunk-major padded weight layout
__global__ void split_w_kernel(const float* __restrict__ W2,
                               const float* __restrict__ W4) {
    int idx = blockIdx.x * blockDim.x + threadIdx.x;   // (n, k)
    if (idx >= DDIM * DDIM) return;
    int n = idx >> 8, k = idx & 255;
    size_t off = (size_t)(k >> 5) * W_CH + (size_t)n * RELEM + (k & 31);
    float w = W2[idx];
    __nv_bfloat16 h = __float2bfloat16(w);
    g_W2h[off] = h;
    g_W2l[off] = __float2bfloat16(w - __bfloat162float(h));
    w = W4[idx];
    h = __float2bfloat16(w);
    g_W4h[off] = h;
    g_W4l[off] = __float2bfloat16(w - __bfloat162float(h));
}

// issue one stage's 4 bulk copies (single thread)
__device__ __forceinline__ void issue_stage_bulk(uint32_t sbase, uint32_t mbar,
                                                 const __nv_bfloat16* inh,
                                                 const __nv_bfloat16* inl,
                                                 const __nv_bfloat16* wh,
                                                 const __nv_bfloat16* wl,
                                                 int arow, int n0, int c) {
    mbar_expect_tx(mbar, 4 * TILE_BYTES);
    size_t aoff = (size_t)c * CH_ELEMS + (size_t)arow * RELEM;
    size_t boff = (size_t)c * W_CH + (size_t)n0 * RELEM;
    bulk_g2s(sbase + SA_H, inh + aoff, TILE_BYTES, mbar);
    bulk_g2s(sbase + SA_L, inl + aoff, TILE_BYTES, mbar);
    bulk_g2s(sbase + SB_H, wh + boff, TILE_BYTES, mbar);
    bulk_g2s(sbase + SB_L, wl + boff, TILE_BYTES, mbar);
}

// compute one BK=32 stage into acc[2][8][4] (3-pass bf16x3). warp tile 32x64.
__device__ __forceinline__ void compute_stage(uint32_t base, int lane, int wm, int wn,
                                              float acc[2][8][4]) {
#pragma unroll
    for (int ks = 0; ks < 2; ks++) {
        uint32_t cb = ks * 32 + ((lane >> 4) * 16);
        uint32_t rlo = (uint32_t)(lane & 15);
        uint32_t ah[2][4], al[2][4];
#pragma unroll
        for (int mt = 0; mt < 2; mt++) {
            uint32_t row = wm * 32 + mt * 16 + rlo;
            ldm_x4(ah[mt], base + SA_H + row * RSTR + cb);
            ldm_x4(al[mt], base + SA_L + row * RSTR + cb);
        }
#pragma unroll
        for (int pr = 0; pr < 4; pr++) {
            uint32_t brow = wn * 64 + pr * 16 + rlo;
            uint32_t bh[4], bl[4];
            ldm_x4(bh, base + SB_H + brow * RSTR + cb);
            ldm_x4(bl, base + SB_L + brow * RSTR + cb);
#pragma unroll
            for (int mt = 0; mt < 2; mt++) {
                mma_bf16(acc[mt][pr * 2],     ah[mt], bh[0], bh[2]);
                mma_bf16(acc[mt][pr * 2 + 1], ah[mt], bh[1], bh[3]);
                mma_bf16(acc[mt][pr * 2],     ah[mt], bl[0], bl[2]);
                mma_bf16(acc[mt][pr * 2 + 1], ah[mt], bl[1], bl[3]);
                mma_bf16(acc[mt][pr * 2],     al[mt], bh[0], bh[2]);
                mma_bf16(acc[mt][pr * 2 + 1], al[mt], bh[1], bh[3]);
            }
        }
    }
}

// ---------------------------------------------------------------------------
// DP iteration: out = relu(a + shift(in)@W2^T + b2).
// grid = (m_tiles, 2 n-halves, 2 lanes). 256 thr, 8 warps = 4m x 2n.
// ---------------------------------------------------------------------------
__global__ __launch_bounds__(NTHR, 2) void dp_iter_kernel(const float* __restrict__ b2,
                                                          int src) {
    extern __shared__ char smem[];
    const uint32_t sb = smem_u32(smem);
    const int tid = threadIdx.x, lane = tid & 31, wid = tid >> 5;
    const int wm = wid >> 1, wn = wid & 1;
    const int m0 = blockIdx.x * BM;
    const int n0 = blockIdx.y * BN;
    const int ln = blockIdx.z;

    const __nv_bfloat16* inh = ln ? g_dn_hi[src] : g_up_hi[src];
    const __nv_bfloat16* inl = ln ? g_dn_lo[src] : g_up_lo[src];
    __nv_bfloat16* outh = ln ? g_dn_hi[src ^ 1] : g_up_hi[src ^ 1];
    __nv_bfloat16* outl = ln ? g_dn_lo[src ^ 1] : g_up_lo[src ^ 1];
    const int shift = ln ? 1 : -1;
    const int bseq = m0 >> 11, l0 = m0 & (LSEQ - 1);
    const int arow = bseq * CHROW + l0 + 1 + shift;   // pad rows absorb boundary

    if (tid == 0) { mbar_init(sb + SM_MBAR, 1); mbar_init(sb + SM_MBAR + 8, 1); }
    __syncthreads();

    float acc[2][8][4];
#pragma unroll
    for (int i = 0; i < 2; i++)
#pragma unroll
        for (int j = 0; j < 8; j++)
#pragma unroll
            for (int q = 0; q < 4; q++) acc[i][j][q] = 0.0f;

    if (tid == 0) {
        issue_stage_bulk(sb,         sb + SM_MBAR,     inh, inl, g_W2h, g_W2l, arow, n0, 0);
        issue_stage_bulk(sb + STAGE, sb + SM_MBAR + 8, inh, inl, g_W2h, g_W2l, arow, n0, 1);
    }

#pragma unroll 1
    for (int c = 0; c < 8; c++) {
        const int buf = c & 1;
        mbar_wait(sb + SM_MBAR + buf * 8, (c >> 1) & 1);
        compute_stage(sb + buf * STAGE, lane, wm, wn, acc);
        __syncthreads();
        if (c < 6 && tid == 0)
            issue_stage_bulk(sb + buf * STAGE, sb + SM_MBAR + buf * 8,
                             inh, inl, g_W2h, g_W2l, arow, n0, c + 2);
    }

    // epilogue: relu(acc + a + b2) -> bf16 hi/lo into padded layout
#pragma unroll
    for (int mt = 0; mt < 2; mt++) {
#pragma unroll
        for (int nt = 0; nt < 8; nt++) {
            int n = n0 + wn * 64 + nt * 8 + (lane & 3) * 2;
            float2 bv = *reinterpret_cast<const float2*>(b2 + n);
#pragma unroll
            for (int h = 0; h < 2; h++) {
                int m = m0 + wm * 32 + mt * 16 + (lane >> 2) + h * 8;
                float2 av = *reinterpret_cast<const float2*>(g_a + (size_t)m * DDIM + n);
                float v0 = fmaxf(acc[mt][nt][2 * h]     + av.x + bv.x, 0.0f);
                float v1 = fmaxf(acc[mt][nt][2 * h + 1] + av.y + bv.y, 0.0f);
                __nv_bfloat162 hv, lv;
                hv.x = __float2bfloat16(v0);
                hv.y = __float2bfloat16(v1);
                lv.x = __float2bfloat16(v0 - __bfloat162float(hv.x));
                lv.y = __float2bfloat16(v1 - __bfloat162float(hv.y));
                size_t off = st_off(m, n);
                *reinterpret_cast<__nv_bfloat162*>(outh + off) = hv;
                *reinterpret_cast<__nv_bfloat162*>(outl + off) = lv;
            }
        }
    }
}

// ---------------------------------------------------------------------------
// final: miu = relu(x@W3^T + b3 + 2*b4 + W4*up[j-1] + W4*down[j+1])
// 16 stages: t<8 -> up (shift -1), t>=8 -> down (shift +1). grid = (m, 2).
// ---------------------------------------------------------------------------
__global__ __launch_bounds__(NTHR, 2) void final_kernel(const float* __restrict__ x,
                                                        const float* __restrict__ W3,
                                                        const float* __restrict__ b3,
                                                        const float* __restrict__ b4,
                                                        float* __restrict__ out,
                                                        int src) {
    extern __shared__ char smem[];
    const uint32_t sb = smem_u32(smem);
    const int tid = threadIdx.x, lane = tid & 31, wid = tid >> 5;
    const int wm = wid >> 1, wn = wid & 1;
    const int m0 = blockIdx.x * BM;
    const int n0 = blockIdx.y * BN;
    const int bseq = m0 >> 11, l0 = m0 & (LSEQ - 1);
    const int arow_up = bseq * CHROW + l0 + 1 - 1;
    const int arow_dn = bseq * CHROW + l0 + 1 + 1;

    if (tid == 0) { mbar_init(sb + SM_MBAR, 1); mbar_init(sb + SM_MBAR + 8, 1); }
    __syncthreads();

    float acc[2][8][4];
#pragma unroll
    for (int i = 0; i < 2; i++)
#pragma unroll
        for (int j = 0; j < 8; j++)
#pragma unroll
            for (int q = 0; q < 4; q++) acc[i][j][q] = 0.0f;

    if (tid == 0) {
        issue_stage_bulk(sb,         sb + SM_MBAR,     g_up_hi[src], g_up_lo[src],
                         g_W4h, g_W4l, arow_up, n0, 0);
        issue_stage_bulk(sb + STAGE, sb + SM_MBAR + 8, g_up_hi[src], g_up_lo[src],
                         g_W4h, g_W4l, arow_up, n0, 1);
    }

#pragma unroll 1
    for (int t = 0; t < 16; t++) {
        const int buf = t & 1;
        mbar_wait(sb + SM_MBAR + buf * 8, (t >> 1) & 1);
        compute_stage(sb + buf * STAGE, lane, wm, wn, acc);
        __syncthreads();
        if (t < 14 && tid == 0) {
            int tn = t + 2;
            int ph = tn >> 3;
            const __nv_bfloat16* inh = ph ? g_dn_hi[src] : g_up_hi[src];
            const __nv_bfloat16* inl = ph ? g_dn_lo[src] : g_up_lo[src];
            issue_stage_bulk(sb + buf * STAGE, sb + SM_MBAR + buf * 8, inh, inl,
                             g_W4h, g_W4l, ph ? arow_dn : arow_up, n0, tn & 7);
        }
    }

    // epilogue: + x@W3^T + b3 + 2*b4, relu, fp32 out (linear layout)
#pragma unroll
    for (int mt = 0; mt < 2; mt++) {
#pragma unroll
        for (int h = 0; h < 2; h++) {
            int m = m0 + wm * 32 + mt * 16 + (lane >> 2) + h * 8;
            int b = m >> 11;
            int l = m & (LSEQ - 1);
            const float* xp = x + (size_t)b * 4 * LSEQ + l;
            float xv[4];
#pragma unroll
            for (int dd = 0; dd < 4; dd++) xv[dd] = xp[dd * LSEQ];
            float* orow = out + (size_t)m * DDIM;
#pragma unroll
            for (int nt = 0; nt < 8; nt++) {
                int n = n0 + wn * 64 + nt * 8 + (lane & 3) * 2;
                float2 b3v = *reinterpret_cast<const float2*>(b3 + n);
                float2 b4v = *reinterpret_cast<const float2*>(b4 + n);
                float v0 = acc[mt][nt][2 * h]     + b3v.x + 2.0f * b4v.x;
                float v1 = acc[mt][nt][2 * h + 1] + b3v.y + 2.0f * b4v.y;
#pragma unroll
                for (int dd = 0; dd < 4; dd++) {
                    v0 = fmaf(xv[dd], W3[n * 4 + dd],       v0);
                    v1 = fmaf(xv[dd], W3[(n + 1) * 4 + dd], v1);
                }
                float2 o = make_float2(fmaxf(v0, 0.0f), fmaxf(v1, 0.0f));
                *reinterpret_cast<float2*>(orow + n) = o;
            }
        }
    }
}

// ---------------------------------------------------------------------------
extern "C" void kernel_launch(void* const* d_in, const int* in_sizes, int n_in,
                              void* d_out, int out_size) {
    const float* x  = (const float*)d_in[0];
    const float* W1 = (const float*)d_in[1];
    const float* b1 = (const float*)d_in[2];
    const float* W2 = (const float*)d_in[3];
    const float* b2 = (const float*)d_in[4];
    const float* W3 = (const float*)d_in[5];
    const float* b3 = (const float*)d_in[6];
    const float* W4 = (const float*)d_in[7];
    const float* b4 = (const float*)d_in[8];
    float* out = (float*)d_out;

    cudaFuncSetAttribute(dp_iter_kernel, cudaFuncAttributeMaxDynamicSharedMemorySize, SMEM_BYTES);
    cudaFuncSetAttribute(final_kernel,   cudaFuncAttributeMaxDynamicSharedMemorySize, SMEM_BYTES);

    int total = MTOT * DDIM;
    prep_kernel<<<(total + 255) / 256, 256>>>(x, W1, b1, b2);
    split_w_kernel<<<(DDIM * DDIM + 255) / 256, 256>>>(W2, W4);

    int src = 0;
    for (int t = 0; t < 7; t++) {
        dp_iter_kernel<<<dim3(MTOT / BM, 2, 2), NTHR, SMEM_BYTES>>>(b2, src);
        src ^= 1;
    }
    final_kernel<<<dim3(MTOT / BM, 2), NTHR, SMEM_BYTES>>>(x, W3, b3, b4, out, src);
}

// round 6
// speedup vs baseline: 2.7373x; 1.1130x over previous
#include <cuda_runtime.h>
#include <cuda_bf16.h>
#include <cstdint>

#define BSZ   16
#define LSEQ  2048
#define DDIM  256
#define MTOT  (BSZ * LSEQ)    // 32768
#define BM    128
#define BN    128
#define NTHR  256

// state layout: chunk-major (8 chunks of 32 k), per row 64 bf16 = [32 hi | 32 lo]
// = 128 bytes, SW128-swizzled (phase chosen per array to match its read shift).
// rows per sequence padded to 2056 (mult of 8), +1 front pad, back pads zero.
#define CHUNKS 8
#define CHROW  2056
#define RELEM  64
#define CH_ELEMS ((size_t)BSZ * CHROW * RELEM)   // 2,105,344
#define W_CH   (256 * RELEM)

// ---------------- global state (static .bss; pad rows stay zero) ----------
__device__ __align__(128) float         g_a[MTOT * DDIM];          // a + b2 (b2 folded)
__device__ __align__(128) __nv_bfloat16 g_up[2][CHUNKS * CH_ELEMS];
__device__ __align__(128) __nv_bfloat16 g_dn[2][CHUNKS * CH_ELEMS];
__device__ __align__(128) __nv_bfloat16 g_W2[CHUNKS * W_CH];
__device__ __align__(128) __nv_bfloat16 g_W4[CHUNKS * W_CH];

// ---------------- helpers ----------------
__device__ __forceinline__ uint32_t smem_u32(const void* p) {
    uint32_t a;
    asm("{ .reg .u64 t; cvta.to.shared.u64 t, %1; cvt.u32.u64 %0, t; }" : "=r"(a) : "l"(p));
    return a;
}
__device__ __forceinline__ void ldm_x4(uint32_t* r, uint32_t addr) {
    asm volatile("ldmatrix.sync.aligned.m8n8.x4.shared.b16 {%0,%1,%2,%3}, [%4];"
                 : "=r"(r[0]), "=r"(r[1]), "=r"(r[2]), "=r"(r[3]) : "r"(addr));
}
__device__ __forceinline__ void mma_bf16(float* c, const uint32_t* a, uint32_t b0, uint32_t b1) {
    asm volatile("mma.sync.aligned.m16n8k16.row.col.f32.bf16.bf16.f32 "
                 "{%0,%1,%2,%3}, {%4,%5,%6,%7}, {%8,%9}, {%0,%1,%2,%3};"
                 : "+f"(c[0]), "+f"(c[1]), "+f"(c[2]), "+f"(c[3])
                 : "r"(a[0]), "r"(a[1]), "r"(a[2]), "r"(a[3]), "r"(b0), "r"(b1));
}
__device__ __forceinline__ void bulk_g2s(uint32_t sdst, const void* gsrc,
                                         uint32_t bytes, uint32_t mbar) {
    asm volatile(
        "cp.async.bulk.shared::cluster.global.mbarrier::complete_tx::bytes [%0], [%1], %2, [%3];"
        :: "r"(sdst), "l"(gsrc), "r"(bytes), "r"(mbar) : "memory");
}
__device__ __forceinline__ void mbar_init(uint32_t mbar, uint32_t cnt) {
    asm volatile("mbarrier.init.shared.b64 [%0], %1;" :: "r"(mbar), "r"(cnt) : "memory");
}
__device__ __forceinline__ void mbar_expect_tx(uint32_t mbar, uint32_t bytes) {
    asm volatile("mbarrier.arrive.expect_tx.shared.b64 _, [%0], %1;"
                 :: "r"(mbar), "r"(bytes) : "memory");
}
__device__ __forceinline__ void mbar_wait(uint32_t mbar, uint32_t parity) {
    uint32_t done;
    asm volatile(
        "{\n\t.reg .pred p;\n\t"
        "mbarrier.try_wait.parity.acquire.cta.shared::cta.b64 p, [%1], %2;\n\t"
        "selp.b32 %0, 1, 0, p;\n\t}"
        : "=r"(done) : "r"(mbar), "r"(parity) : "memory");
    if (!done) {
        asm volatile(
            "{\n\t.reg .pred P1;\n\t"
            "W_%=:\n\t"
            "mbarrier.try_wait.parity.acquire.cta.shared::cta.b64 P1, [%0], %1, 0x989680;\n\t"
            "@P1 bra.uni D_%=;\n\t"
            "bra.uni W_%=;\n\t"
            "D_%=:\n\t}"
            :: "r"(mbar), "r"(parity) : "memory");
    }
}

// ---------------- SMEM layout: 3 stages of 32KB ----------------
static constexpr int SA      = 0;            // A tile: 128 rows x 128B
static constexpr int SB      = 16384;        // B tile: 128 rows x 128B
static constexpr int STAGE   = 32768;
static constexpr int NSTAGE  = 3;
static constexpr int SM_MBAR = NSTAGE * STAGE;            // 98304
static constexpr int SMEM_BYTES = SM_MBAR + NSTAGE * 8;   // 98328
static constexpr uint32_t STAGE_TX = 2 * 16384;

// state element index for (m, n, hi?) with write-phase shift wph (+1 up, -1 dn)
__device__ __forceinline__ size_t st_idx(int m, int n, int ishi, int wph) {
    int l = m & (LSEQ - 1);
    size_t row = (size_t)(m >> 11) * CHROW + l + 1;
    int ph  = ((l + wph) & 7) << 4;
    int raw = (ishi ? 0 : 64) + (n & 31) * 2;
    return (size_t)(n >> 5) * CH_ELEMS + row * RELEM + ((raw ^ ph) >> 1);
}

// ---------------------------------------------------------------------------
// prep: g_a = x@W1^T + b1 + b2 ; state#1 = relu(g_a) split hi/lo, swizzled
// ---------------------------------------------------------------------------
__global__ void prep_kernel(const float* __restrict__ x,
                            const float* __restrict__ W1,
                            const float* __restrict__ b1,
                            const float* __restrict__ b2) {
    int idx = blockIdx.x * blockDim.x + threadIdx.x;
    if (idx >= MTOT * DDIM) return;
    int n = idx & (DDIM - 1);
    int m = idx >> 8;
    int b = m / LSEQ;
    int l = m & (LSEQ - 1);
    const float* xp = x + (size_t)b * 4 * LSEQ + l;
    float s = b1[n] + b2[n];
#pragma unroll
    for (int dd = 0; dd < 4; dd++)
        s = fmaf(xp[dd * LSEQ], W1[n * 4 + dd], s);
    g_a[idx] = s;
    float u0 = fmaxf(s, 0.0f);
    __nv_bfloat16 h  = __float2bfloat16(u0);
    __nv_bfloat16 lo = __float2bfloat16(u0 - __bfloat162float(h));
    g_up[0][st_idx(m, n, 1, +1)] = h;
    g_up[0][st_idx(m, n, 0, +1)] = lo;
    g_dn[0][st_idx(m, n, 1, -1)] = h;
    g_dn[0][st_idx(m, n, 0, -1)] = lo;
}

// split W2/W4 into chunk-major swizzled hi|lo layout (phase = n&7)
__global__ void split_w_kernel(const float* __restrict__ W2,
                               const float* __restrict__ W4) {
    int idx = blockIdx.x * blockDim.x + threadIdx.x;   // (n, k)
    if (idx >= DDIM * DDIM) return;
    int n = idx >> 8, k = idx & 255;
    int ph = (n & 7) << 4;
    size_t base = (size_t)(k >> 5) * W_CH + (size_t)n * RELEM;
    size_t ohi = base + (((k & 31) * 2) ^ ph) / 2;
    size_t olo = base + ((64 + (k & 31) * 2) ^ ph) / 2;
    float w = W2[idx];
    __nv_bfloat16 h = __float2bfloat16(w);
    g_W2[ohi] = h;
    g_W2[olo] = __float2bfloat16(w - __bfloat162float(h));
    w = W4[idx];
    h = __float2bfloat16(w);
    g_W4[ohi] = h;
    g_W4[olo] = __float2bfloat16(w - __bfloat162float(h));
}

// one stage = 2 bulk copies (A state tile, B weight tile), single thread
__device__ __forceinline__ void issue_stage(uint32_t sbase, uint32_t mbar,
                                            const __nv_bfloat16* in,
                                            const __nv_bfloat16* w,
                                            size_t arow, int n0, int c) {
    mbar_expect_tx(mbar, STAGE_TX);
    bulk_g2s(sbase + SA, in + (size_t)c * CH_ELEMS + arow * RELEM, 16384, mbar);
    bulk_g2s(sbase + SB, w + (size_t)c * W_CH + (size_t)n0 * RELEM, 16384, mbar);
}

// compute one BK=32 stage into acc[2][8][4] (3-pass bf16x3). warp tile 32x64.
__device__ __forceinline__ void compute_stage(uint32_t base, int lane, int wm, int wn,
                                              float acc[2][8][4]) {
    const uint32_t swz  = (uint32_t)(lane & 7) << 4;
    const uint32_t rlo  = (uint32_t)(lane & 15);
    const uint32_t hi16 = (uint32_t)(lane >> 4) * 16;
#pragma unroll
    for (int ks = 0; ks < 2; ks++) {
        uint32_t ch = (ks * 32 + hi16) ^ swz;         // hi columns
        uint32_t cl = (64 + ks * 32 + hi16) ^ swz;    // lo columns
        uint32_t ah[2][4], al[2][4];
#pragma unroll
        for (int mt = 0; mt < 2; mt++) {
            uint32_t abase = base + SA + (wm * 32 + mt * 16 + rlo) * 128;
            ldm_x4(ah[mt], abase + ch);
            ldm_x4(al[mt], abase + cl);
        }
#pragma unroll
        for (int pr = 0; pr < 4; pr++) {
            uint32_t bbase = base + SB + (wn * 64 + pr * 16 + rlo) * 128;
            uint32_t bh[4], bl[4];
            ldm_x4(bh, bbase + ch);
            ldm_x4(bl, bbase + cl);
#pragma unroll
            for (int mt = 0; mt < 2; mt++) {
                mma_bf16(acc[mt][pr * 2],     ah[mt], bh[0], bh[2]);
                mma_bf16(acc[mt][pr * 2 + 1], ah[mt], bh[1], bh[3]);
                mma_bf16(acc[mt][pr * 2],     ah[mt], bl[0], bl[2]);
                mma_bf16(acc[mt][pr * 2 + 1], ah[mt], bl[1], bl[3]);
                mma_bf16(acc[mt][pr * 2],     al[mt], bh[0], bh[2]);
                mma_bf16(acc[mt][pr * 2 + 1], al[mt], bh[1], bh[3]);
            }
        }
    }
}

// ---------------------------------------------------------------------------
// DP iteration: out = relu(g_a + shift(in)@W2^T). grid (m_tiles, 2, 2 lanes).
// ---------------------------------------------------------------------------
__global__ __launch_bounds__(NTHR, 2) void dp_iter_kernel(int src) {
    extern __shared__ char smem[];
    const uint32_t sb = smem_u32(smem);
    const int tid = threadIdx.x, lane = tid & 31, wid = tid >> 5;
    const int wm = wid >> 1, wn = wid & 1;
    const int m0 = blockIdx.x * BM;
    const int n0 = blockIdx.y * BN;
    const int ln = blockIdx.z;

    const __nv_bfloat16* in  = ln ? g_dn[src]     : g_up[src];
    __nv_bfloat16*       out = ln ? g_dn[src ^ 1] : g_up[src ^ 1];
    const int shift = ln ? 1 : -1;
    const int wph = -shift;                         // write phase shift for out array
    const size_t arow = (size_t)(m0 >> 11) * CHROW + (m0 & (LSEQ - 1)) + 1 + shift;

    if (tid == 0)
        for (int s = 0; s < NSTAGE; s++) mbar_init(sb + SM_MBAR + s * 8, 1);
    __syncthreads();
    if (tid == 0)
        for (int s = 0; s < NSTAGE; s++)
            issue_stage(sb + s * STAGE, sb + SM_MBAR + s * 8, in, g_W2, arow, n0, s);

    float acc[2][8][4];
#pragma unroll
    for (int i = 0; i < 2; i++)
#pragma unroll
        for (int j = 0; j < 8; j++)
#pragma unroll
            for (int q = 0; q < 4; q++) acc[i][j][q] = 0.0f;

    int buf = 0, par = 0;
#pragma unroll 1
    for (int c = 0; c < 8; c++) {
        mbar_wait(sb + SM_MBAR + buf * 8, par);
        compute_stage(sb + buf * STAGE, lane, wm, wn, acc);
        __syncthreads();
        if (c < 5 && tid == 0)
            issue_stage(sb + buf * STAGE, sb + SM_MBAR + buf * 8, in, g_W2, arow, n0, c + 3);
        if (++buf == NSTAGE) { buf = 0; par ^= 1; }
    }

    // epilogue: relu(acc + g_a) -> hi/lo, swizzled layout
#pragma unroll
    for (int mt = 0; mt < 2; mt++) {
#pragma unroll
        for (int h = 0; h < 2; h++) {
            int m = m0 + wm * 32 + mt * 16 + (lane >> 2) + h * 8;
            int l = m & (LSEQ - 1);
            size_t rowbase = ((size_t)(m >> 11) * CHROW + l + 1) * RELEM;
            int ph = ((l + wph) & 7) << 4;
            const float* arow_p = g_a + (size_t)m * DDIM;
#pragma unroll
            for (int nt = 0; nt < 8; nt++) {
                int n = n0 + wn * 64 + nt * 8 + (lane & 3) * 2;
                float2 av = *reinterpret_cast<const float2*>(arow_p + n);
                float v0 = fmaxf(acc[mt][nt][2 * h]     + av.x, 0.0f);
                float v1 = fmaxf(acc[mt][nt][2 * h + 1] + av.y, 0.0f);
                __nv_bfloat162 hv, lv;
                hv.x = __float2bfloat16(v0);
                hv.y = __float2bfloat16(v1);
                lv.x = __float2bfloat16(v0 - __bfloat162float(hv.x));
                lv.y = __float2bfloat16(v1 - __bfloat162float(hv.y));
                size_t cb = (size_t)(n >> 5) * CH_ELEMS + rowbase;
                int raw = (n & 31) * 2;
                *reinterpret_cast<__nv_bfloat162*>(out + cb + ((raw ^ ph) >> 1))        = hv;
                *reinterpret_cast<__nv_bfloat162*>(out + cb + (((64 + raw) ^ ph) >> 1)) = lv;
            }
        }
    }
}

// ---------------------------------------------------------------------------
// final: miu = relu(x@W3^T + b3 + 2*b4 + W4*up[j-1] + W4*down[j+1])
// 16 stages: t<8 up (shift -1), t>=8 down (shift +1). grid (m_tiles, 2).
// ---------------------------------------------------------------------------
__global__ __launch_bounds__(NTHR, 2) void final_kernel(const float* __restrict__ x,
                                                        const float* __restrict__ W3,
                                                        const float* __restrict__ b3,
                                                        const float* __restrict__ b4,
                                                        float* __restrict__ out,
                                                        int src) {
    extern __shared__ char smem[];
    const uint32_t sb = smem_u32(smem);
    const int tid = threadIdx.x, lane = tid & 31, wid = tid >> 5;
    const int wm = wid >> 1, wn = wid & 1;
    const int m0 = blockIdx.x * BM;
    const int n0 = blockIdx.y * BN;
    const size_t rbase = (size_t)(m0 >> 11) * CHROW + (m0 & (LSEQ - 1)) + 1;
    const size_t arow_up = rbase - 1;
    const size_t arow_dn = rbase + 1;

    if (tid == 0)
        for (int s = 0; s < NSTAGE; s++) mbar_init(sb + SM_MBAR + s * 8, 1);
    __syncthreads();
    if (tid == 0)
        for (int s = 0; s < NSTAGE; s++)
            issue_stage(sb + s * STAGE, sb + SM_MBAR + s * 8, g_up[src], g_W4,
                        arow_up, n0, s);

    float acc[2][8][4];
#pragma unroll
    for (int i = 0; i < 2; i++)
#pragma unroll
        for (int j = 0; j < 8; j++)
#pragma unroll
            for (int q = 0; q < 4; q++) acc[i][j][q] = 0.0f;

    int buf = 0, par = 0;
#pragma unroll 1
    for (int t = 0; t < 16; t++) {
        mbar_wait(sb + SM_MBAR + buf * 8, par);
        compute_stage(sb + buf * STAGE, lane, wm, wn, acc);
        __syncthreads();
        if (t < 13 && tid == 0) {
            int tn = t + 3;
            int ph = tn >> 3;
            issue_stage(sb + buf * STAGE, sb + SM_MBAR + buf * 8,
                        ph ? g_dn[src] : g_up[src], g_W4,
                        ph ? arow_dn : arow_up, n0, tn & 7);
        }
        if (++buf == NSTAGE) { buf = 0; par ^= 1; }
    }

    // epilogue: + x@W3^T + b3 + 2*b4, relu, fp32 out (linear layout)
#pragma unroll
    for (int mt = 0; mt < 2; mt++) {
#pragma unroll
        for (int h = 0; h < 2; h++) {
            int m = m0 + wm * 32 + mt * 16 + (lane >> 2) + h * 8;
            int b = m >> 11;
            int l = m & (LSEQ - 1);
            const float* xp = x + (size_t)b * 4 * LSEQ + l;
            float xv[4];
#pragma unroll
            for (int dd = 0; dd < 4; dd++) xv[dd] = xp[dd * LSEQ];
            float* orow = out + (size_t)m * DDIM;
#pragma unroll
            for (int nt = 0; nt < 8; nt++) {
                int n = n0 + wn * 64 + nt * 8 + (lane & 3) * 2;
                float2 b3v = *reinterpret_cast<const float2*>(b3 + n);
                float2 b4v = *reinterpret_cast<const float2*>(b4 + n);
                float v0 = acc[mt][nt][2 * h]     + b3v.x + 2.0f * b4v.x;
                float v1 = acc[mt][nt][2 * h + 1] + b3v.y + 2.0f * b4v.y;
#pragma unroll
                for (int dd = 0; dd < 4; dd++) {
                    v0 = fmaf(xv[dd], W3[n * 4 + dd],       v0);
                    v1 = fmaf(xv[dd], W3[(n + 1) * 4 + dd], v1);
                }
                float2 o = make_float2(fmaxf(v0, 0.0f), fmaxf(v1, 0.0f));
                *reinterpret_cast<float2*>(orow + n) = o;
            }
        }
    }
}

// ---------------------------------------------------------------------------
extern "C" void kernel_launch(void* const* d_in, const int* in_sizes, int n_in,
                              void* d_out, int out_size) {
    const float* x  = (const float*)d_in[0];
    const float* W1 = (const float*)d_in[1];
    const float* b1 = (const float*)d_in[2];
    const float* W2 = (const float*)d_in[3];
    const float* b2 = (const float*)d_in[4];
    const float* W3 = (const float*)d_in[5];
    const float* b3 = (const float*)d_in[6];
    const float* W4 = (const float*)d_in[7];
    const float* b4 = (const float*)d_in[8];
    float* out = (float*)d_out;

    cudaFuncSetAttribute(dp_iter_kernel, cudaFuncAttributeMaxDynamicSharedMemorySize, SMEM_BYTES);
    cudaFuncSetAttribute(final_kernel,   cudaFuncAttributeMaxDynamicSharedMemorySize, SMEM_BYTES);

    int total = MTOT * DDIM;
    prep_kernel<<<(total + 255) / 256, 256>>>(x, W1, b1, b2);
    split_w_kernel<<<(DDIM * DDIM + 255) / 256, 256>>>(W2, W4);

    int src = 0;
    for (int t = 0; t < 7; t++) {
        dp_iter_kernel<<<dim3(MTOT / BM, 2, 2), NTHR, SMEM_BYTES>>>(src);
        src ^= 1;
    }
    final_kernel<<<dim3(MTOT / BM, 2), NTHR, SMEM_BYTES>>>(x, W3, b3, b4, out, src);
}

// round 7
// speedup vs baseline: 2.7622x; 1.0091x over previous
#include <cuda_runtime.h>
#include <cuda_bf16.h>
#include <cstdint>

#define BSZ   16
#define LSEQ  2048
#define DDIM  256
#define MTOT  (BSZ * LSEQ)    // 32768
#define BM    128
#define BN    128
#define NTHR  256

// state layout: chunk-major (8 chunks of 32 k), per row 64 bf16 = [32 hi | 32 lo]
// = 128 bytes, SW128-swizzled (phase chosen per array to match its read shift).
#define CHUNKS 8
#define CHROW  2056
#define RELEM  64
#define CH_ELEMS ((size_t)BSZ * CHROW * RELEM)
#define W_CH   (256 * RELEM)

// ---------------- global state (static .bss; pad rows stay zero) ----------
__device__ __align__(128) float         g_a[MTOT * DDIM];          // a + b2 folded
__device__ __align__(128) __nv_bfloat16 g_up[2][CHUNKS * CH_ELEMS];
__device__ __align__(128) __nv_bfloat16 g_dn[2][CHUNKS * CH_ELEMS];
__device__ __align__(128) __nv_bfloat16 g_W2[CHUNKS * W_CH];
__device__ __align__(128) __nv_bfloat16 g_W4[CHUNKS * W_CH];

// ---------------- helpers ----------------
__device__ __forceinline__ uint32_t smem_u32(const void* p) {
    uint32_t a;
    asm("{ .reg .u64 t; cvta.to.shared.u64 t, %1; cvt.u32.u64 %0, t; }" : "=r"(a) : "l"(p));
    return a;
}
__device__ __forceinline__ uint32_t elect_one() {
    uint32_t pred;
    asm volatile("{\n\t.reg .pred p;\n\telect.sync _|p, 0xFFFFFFFF;\n\t"
                 "selp.b32 %0, 1, 0, p;\n\t}" : "=r"(pred));
    return pred;
}
__device__ __forceinline__ void ldm_x4(uint32_t* r, uint32_t addr) {
    asm volatile("ldmatrix.sync.aligned.m8n8.x4.shared.b16 {%0,%1,%2,%3}, [%4];"
                 : "=r"(r[0]), "=r"(r[1]), "=r"(r[2]), "=r"(r[3]) : "r"(addr));
}
__device__ __forceinline__ void mma_bf16(float* c, const uint32_t* a, uint32_t b0, uint32_t b1) {
    asm volatile("mma.sync.aligned.m16n8k16.row.col.f32.bf16.bf16.f32 "
                 "{%0,%1,%2,%3}, {%4,%5,%6,%7}, {%8,%9}, {%0,%1,%2,%3};"
                 : "+f"(c[0]), "+f"(c[1]), "+f"(c[2]), "+f"(c[3])
                 : "r"(a[0]), "r"(a[1]), "r"(a[2]), "r"(a[3]), "r"(b0), "r"(b1));
}
__device__ __forceinline__ void bulk_g2s(uint32_t sdst, const void* gsrc,
                                         uint32_t bytes, uint32_t mbar) {
    asm volatile(
        "cp.async.bulk.shared::cluster.global.mbarrier::complete_tx::bytes [%0], [%1], %2, [%3];"
        :: "r"(sdst), "l"(gsrc), "r"(bytes), "r"(mbar) : "memory");
}
__device__ __forceinline__ void mbar_init(uint32_t mbar, uint32_t cnt) {
    asm volatile("mbarrier.init.shared.b64 [%0], %1;" :: "r"(mbar), "r"(cnt) : "memory");
}
__device__ __forceinline__ void mbar_expect_tx(uint32_t mbar, uint32_t bytes) {
    asm volatile("mbarrier.arrive.expect_tx.shared.b64 _, [%0], %1;"
                 :: "r"(mbar), "r"(bytes) : "memory");
}
__device__ __forceinline__ void mbar_arrive(uint32_t mbar) {
    asm volatile("mbarrier.arrive.release.cta.shared::cta.b64 _, [%0];"
                 :: "r"(mbar) : "memory");
}
__device__ __forceinline__ void mbar_wait(uint32_t mbar, uint32_t parity) {
    uint32_t done;
    asm volatile(
        "{\n\t.reg .pred p;\n\t"
        "mbarrier.try_wait.parity.acquire.cta.shared::cta.b64 p, [%1], %2;\n\t"
        "selp.b32 %0, 1, 0, p;\n\t}"
        : "=r"(done) : "r"(mbar), "r"(parity) : "memory");
    if (!done) {
        asm volatile(
            "{\n\t.reg .pred P1;\n\t"
            "W_%=:\n\t"
            "mbarrier.try_wait.parity.acquire.cta.shared::cta.b64 P1, [%0], %1, 0x989680;\n\t"
            "@P1 bra.uni D_%=;\n\t"
            "bra.uni W_%=;\n\t"
            "D_%=:\n\t}"
            :: "r"(mbar), "r"(parity) : "memory");
    }
}

// ---------------- SMEM layout: 3 stages of 32KB + barrier block ----------
static constexpr int SA      = 0;
static constexpr int SB      = 16384;
static constexpr int STAGE   = 32768;
static constexpr int NSTAGE  = 3;
static constexpr int SM_FULL = NSTAGE * STAGE;            // full[i]     @ +i*8
static constexpr int SM_CONS = SM_FULL + NSTAGE * 8;      // consumed[i] @ +i*8
static constexpr int SMEM_BYTES = SM_CONS + NSTAGE * 8;
static constexpr uint32_t STAGE_TX = 2 * 16384;

__device__ __forceinline__ size_t st_idx(int m, int n, int ishi, int wph) {
    int l = m & (LSEQ - 1);
    size_t row = (size_t)(m >> 11) * CHROW + l + 1;
    int ph  = ((l + wph) & 7) << 4;
    int raw = (ishi ? 0 : 64) + (n & 31) * 2;
    return (size_t)(n >> 5) * CH_ELEMS + row * RELEM + ((raw ^ ph) >> 1);
}

// ---------------------------------------------------------------------------
__global__ void prep_kernel(const float* __restrict__ x,
                            const float* __restrict__ W1,
                            const float* __restrict__ b1,
                            const float* __restrict__ b2) {
    int idx = blockIdx.x * blockDim.x + threadIdx.x;
    if (idx >= MTOT * DDIM) return;
    int n = idx & (DDIM - 1);
    int m = idx >> 8;
    int b = m / LSEQ;
    int l = m & (LSEQ - 1);
    const float* xp = x + (size_t)b * 4 * LSEQ + l;
    float s = b1[n] + b2[n];
#pragma unroll
    for (int dd = 0; dd < 4; dd++)
        s = fmaf(xp[dd * LSEQ], W1[n * 4 + dd], s);
    g_a[idx] = s;
    float u0 = fmaxf(s, 0.0f);
    __nv_bfloat16 h  = __float2bfloat16(u0);
    __nv_bfloat16 lo = __float2bfloat16(u0 - __bfloat162float(h));
    g_up[0][st_idx(m, n, 1, +1)] = h;
    g_up[0][st_idx(m, n, 0, +1)] = lo;
    g_dn[0][st_idx(m, n, 1, -1)] = h;
    g_dn[0][st_idx(m, n, 0, -1)] = lo;
}

__global__ void split_w_kernel(const float* __restrict__ W2,
                               const float* __restrict__ W4) {
    int idx = blockIdx.x * blockDim.x + threadIdx.x;   // (n, k)
    if (idx >= DDIM * DDIM) return;
    int n = idx >> 8, k = idx & 255;
    int ph = (n & 7) << 4;
    size_t base = (size_t)(k >> 5) * W_CH + (size_t)n * RELEM;
    size_t ohi = base + (((k & 31) * 2) ^ ph) / 2;
    size_t olo = base + ((64 + (k & 31) * 2) ^ ph) / 2;
    float w = W2[idx];
    __nv_bfloat16 h = __float2bfloat16(w);
    g_W2[ohi] = h;
    g_W2[olo] = __float2bfloat16(w - __bfloat162float(h));
    w = W4[idx];
    h = __float2bfloat16(w);
    g_W4[ohi] = h;
    g_W4[olo] = __float2bfloat16(w - __bfloat162float(h));
}

__device__ __forceinline__ void issue_stage(uint32_t sbase, uint32_t mbar,
                                            const __nv_bfloat16* in,
                                            const __nv_bfloat16* w,
                                            size_t arow, int n0, int c) {
    mbar_expect_tx(mbar, STAGE_TX);
    bulk_g2s(sbase + SA, in + (size_t)c * CH_ELEMS + arow * RELEM, 16384, mbar);
    bulk_g2s(sbase + SB, w + (size_t)c * W_CH + (size_t)n0 * RELEM, 16384, mbar);
}

__device__ __forceinline__ void compute_stage(uint32_t base, int lane, int wm, int wn,
                                              float acc[2][8][4]) {
    const uint32_t swz  = (uint32_t)(lane & 7) << 4;
    const uint32_t rlo  = (uint32_t)(lane & 15);
    const uint32_t hi16 = (uint32_t)(lane >> 4) * 16;
#pragma unroll
    for (int ks = 0; ks < 2; ks++) {
        uint32_t ch = (ks * 32 + hi16) ^ swz;
        uint32_t cl = (64 + ks * 32 + hi16) ^ swz;
        uint32_t ah[2][4], al[2][4];
#pragma unroll
        for (int mt = 0; mt < 2; mt++) {
            uint32_t abase = base + SA + (wm * 32 + mt * 16 + rlo) * 128;
            ldm_x4(ah[mt], abase + ch);
            ldm_x4(al[mt], abase + cl);
        }
#pragma unroll
        for (int pr = 0; pr < 4; pr++) {
            uint32_t bbase = base + SB + (wn * 64 + pr * 16 + rlo) * 128;
            uint32_t bh[4], bl[4];
            ldm_x4(bh, bbase + ch);
            ldm_x4(bl, bbase + cl);
#pragma unroll
            for (int mt = 0; mt < 2; mt++) {
                mma_bf16(acc[mt][pr * 2],     ah[mt], bh[0], bh[2]);
                mma_bf16(acc[mt][pr * 2 + 1], ah[mt], bh[1], bh[3]);
                mma_bf16(acc[mt][pr * 2],     ah[mt], bl[0], bl[2]);
                mma_bf16(acc[mt][pr * 2 + 1], ah[mt], bl[1], bl[3]);
                mma_bf16(acc[mt][pr * 2],     al[mt], bh[0], bh[2]);
                mma_bf16(acc[mt][pr * 2 + 1], al[mt], bh[1], bh[3]);
            }
        }
    }
}

// ---------------------------------------------------------------------------
// DP iteration, desynchronized pipeline (no __syncthreads in mainloop).
// ---------------------------------------------------------------------------
__global__ __launch_bounds__(NTHR, 2) void dp_iter_kernel(int src) {
    extern __shared__ char smem[];
    const uint32_t sb = smem_u32(smem);
    const int tid = threadIdx.x, lane = tid & 31, wid = tid >> 5;
    const int wm = wid >> 1, wn = wid & 1;
    const int m0 = blockIdx.x * BM;
    const int n0 = blockIdx.y * BN;
    const int ln = blockIdx.z;

    const __nv_bfloat16* in  = ln ? g_dn[src]     : g_up[src];
    __nv_bfloat16*       out = ln ? g_dn[src ^ 1] : g_up[src ^ 1];
    const int shift = ln ? 1 : -1;
    const int wph = -shift;
    const size_t arow = (size_t)(m0 >> 11) * CHROW + (m0 & (LSEQ - 1)) + 1 + shift;

    if (tid == 0) {
        for (int s = 0; s < NSTAGE; s++) {
            mbar_init(sb + SM_FULL + s * 8, 1);
            mbar_init(sb + SM_CONS + s * 8, 8);   // one arrive per warp
        }
    }
    __syncthreads();
    if (tid == 0)
        for (int s = 0; s < NSTAGE; s++)
            issue_stage(sb + s * STAGE, sb + SM_FULL + s * 8, in, g_W2, arow, n0, s);

    float acc[2][8][4];
#pragma unroll
    for (int i = 0; i < 2; i++)
#pragma unroll
        for (int j = 0; j < 8; j++)
#pragma unroll
            for (int q = 0; q < 4; q++) acc[i][j][q] = 0.0f;

    const bool prod = (wid == 0) && elect_one();
    int buf = 0, par = 0;
#pragma unroll 1
    for (int c = 0; c < 8; c++) {
        mbar_wait(sb + SM_FULL + buf * 8, par);
        compute_stage(sb + buf * STAGE, lane, wm, wn, acc);
        if (elect_one()) mbar_arrive(sb + SM_CONS + buf * 8);
        if (c < 5 && prod) {
            mbar_wait(sb + SM_CONS + buf * 8, par);
            issue_stage(sb + buf * STAGE, sb + SM_FULL + buf * 8, in, g_W2, arow, n0, c + 3);
        }
        if (++buf == NSTAGE) { buf = 0; par ^= 1; }
    }

    // epilogue: relu(acc + g_a) -> hi/lo, swizzled layout
#pragma unroll
    for (int mt = 0; mt < 2; mt++) {
#pragma unroll
        for (int h = 0; h < 2; h++) {
            int m = m0 + wm * 32 + mt * 16 + (lane >> 2) + h * 8;
            int l = m & (LSEQ - 1);
            size_t rowbase = ((size_t)(m >> 11) * CHROW + l + 1) * RELEM;
            int ph = ((l + wph) & 7) << 4;
            const float* arow_p = g_a + (size_t)m * DDIM;
#pragma unroll
            for (int nt = 0; nt < 8; nt++) {
                int n = n0 + wn * 64 + nt * 8 + (lane & 3) * 2;
                float2 av = *reinterpret_cast<const float2*>(arow_p + n);
                float v0 = fmaxf(acc[mt][nt][2 * h]     + av.x, 0.0f);
                float v1 = fmaxf(acc[mt][nt][2 * h + 1] + av.y, 0.0f);
                __nv_bfloat162 hv, lv;
                hv.x = __float2bfloat16(v0);
                hv.y = __float2bfloat16(v1);
                lv.x = __float2bfloat16(v0 - __bfloat162float(hv.x));
                lv.y = __float2bfloat16(v1 - __bfloat162float(hv.y));
                size_t cb = (size_t)(n >> 5) * CH_ELEMS + rowbase;
                int raw = (n & 31) * 2;
                *reinterpret_cast<__nv_bfloat162*>(out + cb + ((raw ^ ph) >> 1))        = hv;
                *reinterpret_cast<__nv_bfloat162*>(out + cb + (((64 + raw) ^ ph) >> 1)) = lv;
            }
        }
    }
}

// ---------------------------------------------------------------------------
// final kernel, same desynchronized pipeline over 16 stages.
// ---------------------------------------------------------------------------
__global__ __launch_bounds__(NTHR, 2) void final_kernel(const float* __restrict__ x,
                                                        const float* __restrict__ W3,
                                                        const float* __restrict__ b3,
                                                        const float* __restrict__ b4,
                                                        float* __restrict__ out,
                                                        int src) {
    extern __shared__ char smem[];
    const uint32_t sb = smem_u32(smem);
    const int tid = threadIdx.x, lane = tid & 31, wid = tid >> 5;
    const int wm = wid >> 1, wn = wid & 1;
    const int m0 = blockIdx.x * BM;
    const int n0 = blockIdx.y * BN;
    const size_t rbase = (size_t)(m0 >> 11) * CHROW + (m0 & (LSEQ - 1)) + 1;
    const size_t arow_up = rbase - 1;
    const size_t arow_dn = rbase + 1;

    if (tid == 0) {
        for (int s = 0; s < NSTAGE; s++) {
            mbar_init(sb + SM_FULL + s * 8, 1);
            mbar_init(sb + SM_CONS + s * 8, 8);
        }
    }
    __syncthreads();
    if (tid == 0)
        for (int s = 0; s < NSTAGE; s++)
            issue_stage(sb + s * STAGE, sb + SM_FULL + s * 8, g_up[src], g_W4,
                        arow_up, n0, s);

    float acc[2][8][4];
#pragma unroll
    for (int i = 0; i < 2; i++)
#pragma unroll
        for (int j = 0; j < 8; j++)
#pragma unroll
            for (int q = 0; q < 4; q++) acc[i][j][q] = 0.0f;

    const bool prod = (wid == 0) && elect_one();
    int buf = 0, par = 0;
#pragma unroll 1
    for (int t = 0; t < 16; t++) {
        mbar_wait(sb + SM_FULL + buf * 8, par);
        compute_stage(sb + buf * STAGE, lane, wm, wn, acc);
        if (elect_one()) mbar_arrive(sb + SM_CONS + buf * 8);
        if (t < 13 && prod) {
            mbar_wait(sb + SM_CONS + buf * 8, par);
            int tn = t + 3;
            int ph = tn >> 3;
            issue_stage(sb + buf * STAGE, sb + SM_FULL + buf * 8,
                        ph ? g_dn[src] : g_up[src], g_W4,
                        ph ? arow_dn : arow_up, n0, tn & 7);
        }
        if (++buf == NSTAGE) { buf = 0; par ^= 1; }
    }

    // epilogue: + x@W3^T + b3 + 2*b4, relu, fp32 out
#pragma unroll
    for (int mt = 0; mt < 2; mt++) {
#pragma unroll
        for (int h = 0; h < 2; h++) {
            int m = m0 + wm * 32 + mt * 16 + (lane >> 2) + h * 8;
            int b = m >> 11;
            int l = m & (LSEQ - 1);
            const float* xp = x + (size_t)b * 4 * LSEQ + l;
            float xv[4];
#pragma unroll
            for (int dd = 0; dd < 4; dd++) xv[dd] = xp[dd * LSEQ];
            float* orow = out + (size_t)m * DDIM;
#pragma unroll
            for (int nt = 0; nt < 8; nt++) {
                int n = n0 + wn * 64 + nt * 8 + (lane & 3) * 2;
                float2 b3v = *reinterpret_cast<const float2*>(b3 + n);
                float2 b4v = *reinterpret_cast<const float2*>(b4 + n);
                float v0 = acc[mt][nt][2 * h]     + b3v.x + 2.0f * b4v.x;
                float v1 = acc[mt][nt][2 * h + 1] + b3v.y + 2.0f * b4v.y;
#pragma unroll
                for (int dd = 0; dd < 4; dd++) {
                    v0 = fmaf(xv[dd], W3[n * 4 + dd],       v0);
                    v1 = fmaf(xv[dd], W3[(n + 1) * 4 + dd], v1);
                }
                float2 o = make_float2(fmaxf(v0, 0.0f), fmaxf(v1, 0.0f));
                *reinterpret_cast<float2*>(orow + n) = o;
            }
        }
    }
}

// ---------------------------------------------------------------------------
extern "C" void kernel_launch(void* const* d_in, const int* in_sizes, int n_in,
                              void* d_out, int out_size) {
    const float* x  = (const float*)d_in[0];
    const float* W1 = (const float*)d_in[1];
    const float* b1 = (const float*)d_in[2];
    const float* W2 = (const float*)d_in[3];
    const float* b2 = (const float*)d_in[4];
    const float* W3 = (const float*)d_in[5];
    const float* b3 = (const float*)d_in[6];
    const float* W4 = (const float*)d_in[7];
    const float* b4 = (const float*)d_in[8];
    float* out = (float*)d_out;

    cudaFuncSetAttribute(dp_iter_kernel, cudaFuncAttributeMaxDynamicSharedMemorySize, SMEM_BYTES);
    cudaFuncSetAttribute(final_kernel,   cudaFuncAttributeMaxDynamicSharedMemorySize, SMEM_BYTES);

    int total = MTOT * DDIM;
    prep_kernel<<<(total + 255) / 256, 256>>>(x, W1, b1, b2);
    split_w_kernel<<<(DDIM * DDIM + 255) / 256, 256>>>(W2, W4);

    int src = 0;
    for (int t = 0; t < 7; t++) {
        dp_iter_kernel<<<dim3(MTOT / BM, 2, 2), NTHR, SMEM_BYTES>>>(src);
        src ^= 1;
    }
    final_kernel<<<dim3(MTOT / BM, 2), NTHR, SMEM_BYTES>>>(x, W3, b3, b4, out, src);
}

// round 8
// speedup vs baseline: 2.7784x; 1.0059x over previous
#include <cuda_runtime.h>
#include <cuda_bf16.h>
#include <cstdint>

#define BSZ   16
#define LSEQ  2048
#define DDIM  256
#define MTOT  (BSZ * LSEQ)    // 32768
#define BM    128
#define BN    128
#define NTHR  256

// state layout: chunk-major (8 chunks of 32 k), per row 64 bf16 = [32 hi | 32 lo]
// = 128 bytes, SW128-swizzled (phase chosen per array to match its read shift).
#define CHUNKS 8
#define CHROW  2056
#define RELEM  64
#define CH_ELEMS ((size_t)BSZ * CHROW * RELEM)
#define W_CH   (256 * RELEM)

// ---------------- global state (static .bss; pad rows stay zero) ----------
__device__ __align__(128) float         g_a[MTOT * DDIM];          // a + b2 folded
__device__ __align__(128) __nv_bfloat16 g_up[2][CHUNKS * CH_ELEMS];
__device__ __align__(128) __nv_bfloat16 g_dn[2][CHUNKS * CH_ELEMS];
__device__ __align__(128) __nv_bfloat16 g_W2[CHUNKS * W_CH];
__device__ __align__(128) __nv_bfloat16 g_W4[CHUNKS * W_CH];

// ---------------- helpers ----------------
__device__ __forceinline__ uint32_t smem_u32(const void* p) {
    uint32_t a;
    asm("{ .reg .u64 t; cvta.to.shared.u64 t, %1; cvt.u32.u64 %0, t; }" : "=r"(a) : "l"(p));
    return a;
}
__device__ __forceinline__ uint32_t elect_one() {
    uint32_t pred;
    asm volatile("{\n\t.reg .pred p;\n\telect.sync _|p, 0xFFFFFFFF;\n\t"
                 "selp.b32 %0, 1, 0, p;\n\t}" : "=r"(pred));
    return pred;
}
__device__ __forceinline__ void ldm_x4(uint32_t* r, uint32_t addr) {
    asm volatile("ldmatrix.sync.aligned.m8n8.x4.shared.b16 {%0,%1,%2,%3}, [%4];"
                 : "=r"(r[0]), "=r"(r[1]), "=r"(r[2]), "=r"(r[3]) : "r"(addr));
}
__device__ __forceinline__ void mma_bf16(float* c, const uint32_t* a, uint32_t b0, uint32_t b1) {
    asm volatile("mma.sync.aligned.m16n8k16.row.col.f32.bf16.bf16.f32 "
                 "{%0,%1,%2,%3}, {%4,%5,%6,%7}, {%8,%9}, {%0,%1,%2,%3};"
                 : "+f"(c[0]), "+f"(c[1]), "+f"(c[2]), "+f"(c[3])
                 : "r"(a[0]), "r"(a[1]), "r"(a[2]), "r"(a[3]), "r"(b0), "r"(b1));
}
__device__ __forceinline__ void bulk_g2s(uint32_t sdst, const void* gsrc,
                                         uint32_t bytes, uint32_t mbar) {
    asm volatile(
        "cp.async.bulk.shared::cluster.global.mbarrier::complete_tx::bytes [%0], [%1], %2, [%3];"
        :: "r"(sdst), "l"(gsrc), "r"(bytes), "r"(mbar) : "memory");
}
__device__ __forceinline__ void mbar_init(uint32_t mbar, uint32_t cnt) {
    asm volatile("mbarrier.init.shared.b64 [%0], %1;" :: "r"(mbar), "r"(cnt) : "memory");
}
__device__ __forceinline__ void mbar_expect_tx(uint32_t mbar, uint32_t bytes) {
    asm volatile("mbarrier.arrive.expect_tx.shared.b64 _, [%0], %1;"
                 :: "r"(mbar), "r"(bytes) : "memory");
}
__device__ __forceinline__ void mbar_arrive(uint32_t mbar) {
    asm volatile("mbarrier.arrive.release.cta.shared::cta.b64 _, [%0];"
                 :: "r"(mbar) : "memory");
}
__device__ __forceinline__ void mbar_wait(uint32_t mbar, uint32_t parity) {
    uint32_t done;
    asm volatile(
        "{\n\t.reg .pred p;\n\t"
        "mbarrier.try_wait.parity.acquire.cta.shared::cta.b64 p, [%1], %2;\n\t"
        "selp.b32 %0, 1, 0, p;\n\t}"
        : "=r"(done) : "r"(mbar), "r"(parity) : "memory");
    if (!done) {
        asm volatile(
            "{\n\t.reg .pred P1;\n\t"
            "W_%=:\n\t"
            "mbarrier.try_wait.parity.acquire.cta.shared::cta.b64 P1, [%0], %1, 0x989680;\n\t"
            "@P1 bra.uni D_%=;\n\t"
            "bra.uni W_%=;\n\t"
            "D_%=:\n\t}"
            :: "r"(mbar), "r"(parity) : "memory");
    }
}

// ---------------- SMEM layout: 3 stages of 32KB + barrier block ----------
static constexpr int SA      = 0;
static constexpr int SB      = 16384;
static constexpr int STAGE   = 32768;
static constexpr int NSTAGE  = 3;
static constexpr int SM_FULL = NSTAGE * STAGE;
static constexpr int SM_CONS = SM_FULL + NSTAGE * 8;
static constexpr int SMEM_BYTES = SM_CONS + NSTAGE * 8;
static constexpr uint32_t STAGE_TX = 2 * 16384;

__device__ __forceinline__ size_t st_idx(int m, int n, int ishi, int wph) {
    int l = m & (LSEQ - 1);
    size_t row = (size_t)(m >> 11) * CHROW + l + 1;
    int ph  = ((l + wph) & 7) << 4;
    int raw = (ishi ? 0 : 64) + (n & 31) * 2;
    return (size_t)(n >> 5) * CH_ELEMS + row * RELEM + ((raw ^ ph) >> 1);
}

// ---------------------------------------------------------------------------
__global__ void prep_kernel(const float* __restrict__ x,
                            const float* __restrict__ W1,
                            const float* __restrict__ b1,
                            const float* __restrict__ b2) {
    int idx = blockIdx.x * blockDim.x + threadIdx.x;
    if (idx >= MTOT * DDIM) return;
    int n = idx & (DDIM - 1);
    int m = idx >> 8;
    int b = m / LSEQ;
    int l = m & (LSEQ - 1);
    const float* xp = x + (size_t)b * 4 * LSEQ + l;
    float s = b1[n] + b2[n];
#pragma unroll
    for (int dd = 0; dd < 4; dd++)
        s = fmaf(xp[dd * LSEQ], W1[n * 4 + dd], s);
    g_a[idx] = s;
    float u0 = fmaxf(s, 0.0f);
    __nv_bfloat16 h  = __float2bfloat16(u0);
    __nv_bfloat16 lo = __float2bfloat16(u0 - __bfloat162float(h));
    g_up[0][st_idx(m, n, 1, +1)] = h;
    g_up[0][st_idx(m, n, 0, +1)] = lo;
    g_dn[0][st_idx(m, n, 1, -1)] = h;
    g_dn[0][st_idx(m, n, 0, -1)] = lo;
}

__global__ void split_w_kernel(const float* __restrict__ W2,
                               const float* __restrict__ W4) {
    int idx = blockIdx.x * blockDim.x + threadIdx.x;   // (n, k)
    if (idx >= DDIM * DDIM) return;
    int n = idx >> 8, k = idx & 255;
    int ph = (n & 7) << 4;
    size_t base = (size_t)(k >> 5) * W_CH + (size_t)n * RELEM;
    size_t ohi = base + (((k & 31) * 2) ^ ph) / 2;
    size_t olo = base + ((64 + (k & 31) * 2) ^ ph) / 2;
    float w = W2[idx];
    __nv_bfloat16 h = __float2bfloat16(w);
    g_W2[ohi] = h;
    g_W2[olo] = __float2bfloat16(w - __bfloat162float(h));
    w = W4[idx];
    h = __float2bfloat16(w);
    g_W4[ohi] = h;
    g_W4[olo] = __float2bfloat16(w - __bfloat162float(h));
}

__device__ __forceinline__ void issue_stage(uint32_t sbase, uint32_t mbar,
                                            const __nv_bfloat16* in,
                                            const __nv_bfloat16* w,
                                            size_t arow, int n0, int c) {
    mbar_expect_tx(mbar, STAGE_TX);
    bulk_g2s(sbase + SA, in + (size_t)c * CH_ELEMS + arow * RELEM, 16384, mbar);
    bulk_g2s(sbase + SB, w + (size_t)c * W_CH + (size_t)n0 * RELEM, 16384, mbar);
}

// compute one BK=32 stage; MMAs reordered pass-major over pr-pairs so each
// accumulator quad is revisited only after 8 intervening MMAs (breaks RAW chain).
__device__ __forceinline__ void compute_stage(uint32_t base, int lane, int wm, int wn,
                                              float acc[2][8][4]) {
    const uint32_t swz  = (uint32_t)(lane & 7) << 4;
    const uint32_t rlo  = (uint32_t)(lane & 15);
    const uint32_t hi16 = (uint32_t)(lane >> 4) * 16;
#pragma unroll
    for (int ks = 0; ks < 2; ks++) {
        uint32_t ch = (ks * 32 + hi16) ^ swz;
        uint32_t cl = (64 + ks * 32 + hi16) ^ swz;
        uint32_t ah[2][4], al[2][4];
#pragma unroll
        for (int mt = 0; mt < 2; mt++) {
            uint32_t abase = base + SA + (wm * 32 + mt * 16 + rlo) * 128;
            ldm_x4(ah[mt], abase + ch);
            ldm_x4(al[mt], abase + cl);
        }
#pragma unroll
        for (int pp = 0; pp < 2; pp++) {           // pr pairs: {0,1}, {2,3}
            uint32_t b0base = base + SB + ((wn * 4 + pp * 2) * 16 + rlo) * 128;
            uint32_t b1base = base + SB + ((wn * 4 + pp * 2 + 1) * 16 + rlo) * 128;
            uint32_t bh0[4], bl0[4], bh1[4], bl1[4];
            ldm_x4(bh0, b0base + ch);
            ldm_x4(bl0, b0base + cl);
            ldm_x4(bh1, b1base + ch);
            ldm_x4(bl1, b1base + cl);
            const int p0 = pp * 4, p1 = pp * 4 + 2;
            // pass 1: A_hi * B_hi  (8 MMAs, 8 distinct acc quads)
#pragma unroll
            for (int mt = 0; mt < 2; mt++) {
                mma_bf16(acc[mt][p0],     ah[mt], bh0[0], bh0[2]);
                mma_bf16(acc[mt][p0 + 1], ah[mt], bh0[1], bh0[3]);
                mma_bf16(acc[mt][p1],     ah[mt], bh1[0], bh1[2]);
                mma_bf16(acc[mt][p1 + 1], ah[mt], bh1[1], bh1[3]);
            }
            // pass 2: A_hi * B_lo
#pragma unroll
            for (int mt = 0; mt < 2; mt++) {
                mma_bf16(acc[mt][p0],     ah[mt], bl0[0], bl0[2]);
                mma_bf16(acc[mt][p0 + 1], ah[mt], bl0[1], bl0[3]);
                mma_bf16(acc[mt][p1],     ah[mt], bl1[0], bl1[2]);
                mma_bf16(acc[mt][p1 + 1], ah[mt], bl1[1], bl1[3]);
            }
            // pass 3: A_lo * B_hi
#pragma unroll
            for (int mt = 0; mt < 2; mt++) {
                mma_bf16(acc[mt][p0],     al[mt], bh0[0], bh0[2]);
                mma_bf16(acc[mt][p0 + 1], al[mt], bh0[1], bh0[3]);
                mma_bf16(acc[mt][p1],     al[mt], bh1[0], bh1[2]);
                mma_bf16(acc[mt][p1 + 1], al[mt], bh1[1], bh1[3]);
            }
        }
    }
}

// ---------------------------------------------------------------------------
// DP iteration, desynchronized pipeline.
// ---------------------------------------------------------------------------
__global__ __launch_bounds__(NTHR, 2) void dp_iter_kernel(int src) {
    extern __shared__ char smem[];
    const uint32_t sb = smem_u32(smem);
    const int tid = threadIdx.x, lane = tid & 31, wid = tid >> 5;
    const int wm = wid >> 1, wn = wid & 1;
    const int m0 = blockIdx.x * BM;
    const int n0 = blockIdx.y * BN;
    const int ln = blockIdx.z;

    const __nv_bfloat16* in  = ln ? g_dn[src]     : g_up[src];
    __nv_bfloat16*       out = ln ? g_dn[src ^ 1] : g_up[src ^ 1];
    const int shift = ln ? 1 : -1;
    const int wph = -shift;
    const size_t arow = (size_t)(m0 >> 11) * CHROW + (m0 & (LSEQ - 1)) + 1 + shift;

    if (tid == 0) {
        for (int s = 0; s < NSTAGE; s++) {
            mbar_init(sb + SM_FULL + s * 8, 1);
            mbar_init(sb + SM_CONS + s * 8, 8);
        }
    }
    __syncthreads();
    if (tid == 0)
        for (int s = 0; s < NSTAGE; s++)
            issue_stage(sb + s * STAGE, sb + SM_FULL + s * 8, in, g_W2, arow, n0, s);

    float acc[2][8][4];
#pragma unroll
    for (int i = 0; i < 2; i++)
#pragma unroll
        for (int j = 0; j < 8; j++)
#pragma unroll
            for (int q = 0; q < 4; q++) acc[i][j][q] = 0.0f;

    const bool prod = (wid == 0) && elect_one();
    int buf = 0, par = 0;
#pragma unroll 1
    for (int c = 0; c < 8; c++) {
        mbar_wait(sb + SM_FULL + buf * 8, par);
        compute_stage(sb + buf * STAGE, lane, wm, wn, acc);
        if (elect_one()) mbar_arrive(sb + SM_CONS + buf * 8);
        if (c < 5 && prod) {
            mbar_wait(sb + SM_CONS + buf * 8, par);
            issue_stage(sb + buf * STAGE, sb + SM_FULL + buf * 8, in, g_W2, arow, n0, c + 3);
        }
        if (++buf == NSTAGE) { buf = 0; par ^= 1; }
    }

    // epilogue: relu(acc + g_a) -> hi/lo, swizzled layout
#pragma unroll
    for (int mt = 0; mt < 2; mt++) {
#pragma unroll
        for (int h = 0; h < 2; h++) {
            int m = m0 + wm * 32 + mt * 16 + (lane >> 2) + h * 8;
            int l = m & (LSEQ - 1);
            size_t rowbase = ((size_t)(m >> 11) * CHROW + l + 1) * RELEM;
            int ph = ((l + wph) & 7) << 4;
            const float* arow_p = g_a + (size_t)m * DDIM;
#pragma unroll
            for (int nt = 0; nt < 8; nt++) {
                int n = n0 + wn * 64 + nt * 8 + (lane & 3) * 2;
                float2 av = *reinterpret_cast<const float2*>(arow_p + n);
                float v0 = fmaxf(acc[mt][nt][2 * h]     + av.x, 0.0f);
                float v1 = fmaxf(acc[mt][nt][2 * h + 1] + av.y, 0.0f);
                __nv_bfloat162 hv, lv;
                hv.x = __float2bfloat16(v0);
                hv.y = __float2bfloat16(v1);
                lv.x = __float2bfloat16(v0 - __bfloat162float(hv.x));
                lv.y = __float2bfloat16(v1 - __bfloat162float(hv.y));
                size_t cb = (size_t)(n >> 5) * CH_ELEMS + rowbase;
                int raw = (n & 31) * 2;
                *reinterpret_cast<__nv_bfloat162*>(out + cb + ((raw ^ ph) >> 1))        = hv;
                *reinterpret_cast<__nv_bfloat162*>(out + cb + (((64 + raw) ^ ph) >> 1)) = lv;
            }
        }
    }
}

// ---------------------------------------------------------------------------
// final kernel, same pipeline over 16 stages.
// ---------------------------------------------------------------------------
__global__ __launch_bounds__(NTHR, 2) void final_kernel(const float* __restrict__ x,
                                                        const float* __restrict__ W3,
                                                        const float* __restrict__ b3,
                                                        const float* __restrict__ b4,
                                                        float* __restrict__ out,
                                                        int src) {
    extern __shared__ char smem[];
    const uint32_t sb = smem_u32(smem);
    const int tid = threadIdx.x, lane = tid & 31, wid = tid >> 5;
    const int wm = wid >> 1, wn = wid & 1;
    const int m0 = blockIdx.x * BM;
    const int n0 = blockIdx.y * BN;
    const size_t rbase = (size_t)(m0 >> 11) * CHROW + (m0 & (LSEQ - 1)) + 1;
    const size_t arow_up = rbase - 1;
    const size_t arow_dn = rbase + 1;

    if (tid == 0) {
        for (int s = 0; s < NSTAGE; s++) {
            mbar_init(sb + SM_FULL + s * 8, 1);
            mbar_init(sb + SM_CONS + s * 8, 8);
        }
    }
    __syncthreads();
    if (tid == 0)
        for (int s = 0; s < NSTAGE; s++)
            issue_stage(sb + s * STAGE, sb + SM_FULL + s * 8, g_up[src], g_W4,
                        arow_up, n0, s);

    float acc[2][8][4];
#pragma unroll
    for (int i = 0; i < 2; i++)
#pragma unroll
        for (int j = 0; j < 8; j++)
#pragma unroll
            for (int q = 0; q < 4; q++) acc[i][j][q] = 0.0f;

    const bool prod = (wid == 0) && elect_one();
    int buf = 0, par = 0;
#pragma unroll 1
    for (int t = 0; t < 16; t++) {
        mbar_wait(sb + SM_FULL + buf * 8, par);
        compute_stage(sb + buf * STAGE, lane, wm, wn, acc);
        if (elect_one()) mbar_arrive(sb + SM_CONS + buf * 8);
        if (t < 13 && prod) {
            mbar_wait(sb + SM_CONS + buf * 8, par);
            int tn = t + 3;
            int ph = tn >> 3;
            issue_stage(sb + buf * STAGE, sb + SM_FULL + buf * 8,
                        ph ? g_dn[src] : g_up[src], g_W4,
                        ph ? arow_dn : arow_up, n0, tn & 7);
        }
        if (++buf == NSTAGE) { buf = 0; par ^= 1; }
    }

    // epilogue: + x@W3^T + b3 + 2*b4, relu, fp32 out
#pragma unroll
    for (int mt = 0; mt < 2; mt++) {
#pragma unroll
        for (int h = 0; h < 2; h++) {
            int m = m0 + wm * 32 + mt * 16 + (lane >> 2) + h * 8;
            int b = m >> 11;
            int l = m & (LSEQ - 1);
            const float* xp = x + (size_t)b * 4 * LSEQ + l;
            float xv[4];
#pragma unroll
            for (int dd = 0; dd < 4; dd++) xv[dd] = xp[dd * LSEQ];
            float* orow = out + (size_t)m * DDIM;
#pragma unroll
            for (int nt = 0; nt < 8; nt++) {
                int n = n0 + wn * 64 + nt * 8 + (lane & 3) * 2;
                float2 b3v = *reinterpret_cast<const float2*>(b3 + n);
                float2 b4v = *reinterpret_cast<const float2*>(b4 + n);
                float v0 = acc[mt][nt][2 * h]     + b3v.x + 2.0f * b4v.x;
                float v1 = acc[mt][nt][2 * h + 1] + b3v.y + 2.0f * b4v.y;
#pragma unroll
                for (int dd = 0; dd < 4; dd++) {
                    v0 = fmaf(xv[dd], W3[n * 4 + dd],       v0);
                    v1 = fmaf(xv[dd], W3[(n + 1) * 4 + dd], v1);
                }
                float2 o = make_float2(fmaxf(v0, 0.0f), fmaxf(v1, 0.0f));
                *reinterpret_cast<float2*>(orow + n) = o;
            }
        }
    }
}

// ---------------------------------------------------------------------------
extern "C" void kernel_launch(void* const* d_in, const int* in_sizes, int n_in,
                              void* d_out, int out_size) {
    const float* x  = (const float*)d_in[0];
    const float* W1 = (const float*)d_in[1];
    const float* b1 = (const float*)d_in[2];
    const float* W2 = (const float*)d_in[3];
    const float* b2 = (const float*)d_in[4];
    const float* W3 = (const float*)d_in[5];
    const float* b3 = (const float*)d_in[6];
    const float* W4 = (const float*)d_in[7];
    const float* b4 = (const float*)d_in[8];
    float* out = (float*)d_out;

    cudaFuncSetAttribute(dp_iter_kernel, cudaFuncAttributeMaxDynamicSharedMemorySize, SMEM_BYTES);
    cudaFuncSetAttribute(final_kernel,   cudaFuncAttributeMaxDynamicSharedMemorySize, SMEM_BYTES);

    int total = MTOT * DDIM;
    prep_kernel<<<(total + 255) / 256, 256>>>(x, W1, b1, b2);
    split_w_kernel<<<(DDIM * DDIM + 255) / 256, 256>>>(W2, W4);

    int src = 0;
    for (int t = 0; t < 7; t++) {
        dp_iter_kernel<<<dim3(MTOT / BM, 2, 2), NTHR, SMEM_BYTES>>>(src);
        src ^= 1;
    }
    final_kernel<<<dim3(MTOT / BM, 2), NTHR, SMEM_BYTES>>>(x, W3, b3, b4, out, src);
}

// round 9
// speedup vs baseline: 3.8401x; 1.3822x over previous
#include <cuda_runtime.h>
#include <cuda_fp16.h>
#include <cstdint>

#define BSZ   16
#define LSEQ  2048
#define DDIM  256
#define MTOT  (BSZ * LSEQ)    // 32768
#define BM    128
#define BN    128
#define NTHR  256

// A (state): single fp16, 4 super-chunks of k64; row = 64 fp16 = 128B, SW128
// phase baked per (l + wph). B (weights): fp16 hi|lo, 8 chunks of k32, rows
// 128B = [32 Bh | 32 Bl], phase (n&7).
#define CHROW  2056
#define A_CH_ELEMS ((size_t)BSZ * CHROW * 64)   // per super-chunk
#define W_CH   (256 * 64)                        // per weight chunk (fp16 elems)

// ---------------- global state (static .bss; pad rows stay zero) ----------
__device__ __align__(128) float  g_a[MTOT * DDIM];              // a + b2 folded
__device__ __align__(128) __half g_up[2][4 * A_CH_ELEMS];
__device__ __align__(128) __half g_dn[2][4 * A_CH_ELEMS];
__device__ __align__(128) __half g_W2[8 * W_CH];
__device__ __align__(128) __half g_W4[8 * W_CH];

// ---------------- helpers ----------------
__device__ __forceinline__ uint32_t smem_u32(const void* p) {
    uint32_t a;
    asm("{ .reg .u64 t; cvta.to.shared.u64 t, %1; cvt.u32.u64 %0, t; }" : "=r"(a) : "l"(p));
    return a;
}
__device__ __forceinline__ uint32_t elect_one() {
    uint32_t pred;
    asm volatile("{\n\t.reg .pred p;\n\telect.sync _|p, 0xFFFFFFFF;\n\t"
                 "selp.b32 %0, 1, 0, p;\n\t}" : "=r"(pred));
    return pred;
}
__device__ __forceinline__ void ldm_x4(uint32_t* r, uint32_t addr) {
    asm volatile("ldmatrix.sync.aligned.m8n8.x4.shared.b16 {%0,%1,%2,%3}, [%4];"
                 : "=r"(r[0]), "=r"(r[1]), "=r"(r[2]), "=r"(r[3]) : "r"(addr));
}
__device__ __forceinline__ void mma_f16(float* c, const uint32_t* a, uint32_t b0, uint32_t b1) {
    asm volatile("mma.sync.aligned.m16n8k16.row.col.f32.f16.f16.f32 "
                 "{%0,%1,%2,%3}, {%4,%5,%6,%7}, {%8,%9}, {%0,%1,%2,%3};"
                 : "+f"(c[0]), "+f"(c[1]), "+f"(c[2]), "+f"(c[3])
                 : "r"(a[0]), "r"(a[1]), "r"(a[2]), "r"(a[3]), "r"(b0), "r"(b1));
}
__device__ __forceinline__ void bulk_g2s(uint32_t sdst, const void* gsrc,
                                         uint32_t bytes, uint32_t mbar) {
    asm volatile(
        "cp.async.bulk.shared::cluster.global.mbarrier::complete_tx::bytes [%0], [%1], %2, [%3];"
        :: "r"(sdst), "l"(gsrc), "r"(bytes), "r"(mbar) : "memory");
}
__device__ __forceinline__ void mbar_init(uint32_t mbar, uint32_t cnt) {
    asm volatile("mbarrier.init.shared.b64 [%0], %1;" :: "r"(mbar), "r"(cnt) : "memory");
}
__device__ __forceinline__ void mbar_expect_tx(uint32_t mbar, uint32_t bytes) {
    asm volatile("mbarrier.arrive.expect_tx.shared.b64 _, [%0], %1;"
                 :: "r"(mbar), "r"(bytes) : "memory");
}
__device__ __forceinline__ void mbar_arrive(uint32_t mbar) {
    asm volatile("mbarrier.arrive.release.cta.shared::cta.b64 _, [%0];"
                 :: "r"(mbar) : "memory");
}
__device__ __forceinline__ void mbar_wait(uint32_t mbar, uint32_t parity) {
    uint32_t done;
    asm volatile(
        "{\n\t.reg .pred p;\n\t"
        "mbarrier.try_wait.parity.acquire.cta.shared::cta.b64 p, [%1], %2;\n\t"
        "selp.b32 %0, 1, 0, p;\n\t}"
        : "=r"(done) : "r"(mbar), "r"(parity) : "memory");
    if (!done) {
        asm volatile(
            "{\n\t.reg .pred P1;\n\t"
            "W_%=:\n\t"
            "mbarrier.try_wait.parity.acquire.cta.shared::cta.b64 P1, [%0], %1, 0x989680;\n\t"
            "@P1 bra.uni D_%=;\n\t"
            "bra.uni W_%=;\n\t"
            "D_%=:\n\t}"
            :: "r"(mbar), "r"(parity) : "memory");
    }
}

// ---------------- SMEM layout ----------------
static constexpr int SB       = 0;                 // B ring: 3 x 16KB
static constexpr int SA       = 3 * 16384;         // A ring: 2 x 16KB
static constexpr int SM_FULLB = SA + 2 * 16384;    // 81920
static constexpr int SM_CONSB = SM_FULLB + 3 * 8;
static constexpr int SM_FULLA = SM_CONSB + 3 * 8;
static constexpr int SM_CONSA = SM_FULLA + 2 * 8;
static constexpr int SMEM_BYTES = SM_CONSA + 2 * 8;   // 82000

// state element index (fp16 units) for (m, n), write-phase wph
__device__ __forceinline__ size_t st_idx(int m, int n, int wph) {
    int l = m & (LSEQ - 1);
    size_t row = (size_t)(m >> 11) * CHROW + l + 1;
    int ph  = ((l + wph) & 7) << 4;
    int raw = (n & 63) * 2;
    return (size_t)(n >> 6) * A_CH_ELEMS + row * 64 + ((raw ^ ph) >> 1);
}

// ---------------------------------------------------------------------------
__global__ void prep_kernel(const float* __restrict__ x,
                            const float* __restrict__ W1,
                            const float* __restrict__ b1,
                            const float* __restrict__ b2) {
    int idx = blockIdx.x * blockDim.x + threadIdx.x;
    if (idx >= MTOT * DDIM) return;
    int n = idx & (DDIM - 1);
    int m = idx >> 8;
    int b = m / LSEQ;
    int l = m & (LSEQ - 1);
    const float* xp = x + (size_t)b * 4 * LSEQ + l;
    float s = b1[n] + b2[n];
#pragma unroll
    for (int dd = 0; dd < 4; dd++)
        s = fmaf(xp[dd * LSEQ], W1[n * 4 + dd], s);
    g_a[idx] = s;
    __half h = __float2half(fmaxf(s, 0.0f));
    g_up[0][st_idx(m, n, +1)] = h;
    g_dn[0][st_idx(m, n, -1)] = h;
}

// split W2/W4 into fp16 hi+lo chunk-major swizzled layout
__global__ void split_w_kernel(const float* __restrict__ W2,
                               const float* __restrict__ W4) {
    int idx = blockIdx.x * blockDim.x + threadIdx.x;   // (n, k)
    if (idx >= DDIM * DDIM) return;
    int n = idx >> 8, k = idx & 255;
    int ph = (n & 7) << 4;
    size_t base = (size_t)(k >> 5) * W_CH + (size_t)n * 64;
    size_t ohi = base + ((((k & 31) * 2)) ^ ph) / 2;
    size_t olo = base + ((64 + (k & 31) * 2) ^ ph) / 2;
    float w = W2[idx];
    __half h = __float2half(w);
    g_W2[ohi] = h;
    g_W2[olo] = __float2half(w - __half2float(h));
    w = W4[idx];
    h = __float2half(w);
    g_W4[ohi] = h;
    g_W4[olo] = __float2half(w - __half2float(h));
}

__device__ __forceinline__ void issue_B(uint32_t sdst, uint32_t mbar,
                                        const __half* w, int n0, int c) {
    mbar_expect_tx(mbar, 16384);
    bulk_g2s(sdst, w + (size_t)c * W_CH + (size_t)n0 * 64, 16384, mbar);
}
__device__ __forceinline__ void issue_A(uint32_t sdst, uint32_t mbar,
                                        const __half* in, size_t arow, int sc) {
    mbar_expect_tx(mbar, 16384);
    bulk_g2s(sdst, in + (size_t)sc * A_CH_ELEMS + arow * 64, 16384, mbar);
}

// one BK=32 stage, fp16 2-pass (Ah*Bh + Ah*Bl). khalf selects k32 half of the
// A super-chunk row. warp tile 32x64.
__device__ __forceinline__ void compute_stage(uint32_t baseA, uint32_t baseB, int khalf,
                                              int lane, int wm, int wn, float acc[2][8][4]) {
    const uint32_t swz  = (uint32_t)(lane & 7) << 4;
    const uint32_t rlo  = (uint32_t)(lane & 15);
    const uint32_t hi16 = (uint32_t)(lane >> 4) * 16;
#pragma unroll
    for (int ks = 0; ks < 2; ks++) {
        uint32_t chA = ((uint32_t)(khalf * 64 + ks * 32) + hi16) ^ swz;
        uint32_t chB = ((uint32_t)(ks * 32) + hi16) ^ swz;
        uint32_t clB = ((uint32_t)(64 + ks * 32) + hi16) ^ swz;
        uint32_t ah[2][4];
#pragma unroll
        for (int mt = 0; mt < 2; mt++)
            ldm_x4(ah[mt], baseA + (wm * 32 + mt * 16 + rlo) * 128 + chA);
#pragma unroll
        for (int pp = 0; pp < 2; pp++) {
            uint32_t b0base = baseB + ((wn * 4 + pp * 2) * 16 + rlo) * 128;
            uint32_t b1base = baseB + ((wn * 4 + pp * 2 + 1) * 16 + rlo) * 128;
            uint32_t bh0[4], bl0[4], bh1[4], bl1[4];
            ldm_x4(bh0, b0base + chB);
            ldm_x4(bl0, b0base + clB);
            ldm_x4(bh1, b1base + chB);
            ldm_x4(bl1, b1base + clB);
            const int p0 = pp * 4, p1 = pp * 4 + 2;
#pragma unroll
            for (int mt = 0; mt < 2; mt++) {
                mma_f16(acc[mt][p0],     ah[mt], bh0[0], bh0[2]);
                mma_f16(acc[mt][p0 + 1], ah[mt], bh0[1], bh0[3]);
                mma_f16(acc[mt][p1],     ah[mt], bh1[0], bh1[2]);
                mma_f16(acc[mt][p1 + 1], ah[mt], bh1[1], bh1[3]);
            }
#pragma unroll
            for (int mt = 0; mt < 2; mt++) {
                mma_f16(acc[mt][p0],     ah[mt], bl0[0], bl0[2]);
                mma_f16(acc[mt][p0 + 1], ah[mt], bl0[1], bl0[3]);
                mma_f16(acc[mt][p1],     ah[mt], bl1[0], bl1[2]);
                mma_f16(acc[mt][p1 + 1], ah[mt], bl1[1], bl1[3]);
            }
        }
    }
}

// ---------------------------------------------------------------------------
// DP iteration: out = relu(g_a + shift(in)@W2^T). grid (m_tiles, 2, 2 lanes).
// ---------------------------------------------------------------------------
__global__ __launch_bounds__(NTHR, 2) void dp_iter_kernel(int src) {
    extern __shared__ char smem[];
    const uint32_t sb = smem_u32(smem);
    const int tid = threadIdx.x, lane = tid & 31, wid = tid >> 5;
    const int wm = wid >> 1, wn = wid & 1;
    const int m0 = blockIdx.x * BM;
    const int n0 = blockIdx.y * BN;
    const int ln = blockIdx.z;

    const __half* in  = ln ? g_dn[src]     : g_up[src];
    __half*       out = ln ? g_dn[src ^ 1] : g_up[src ^ 1];
    const int shift = ln ? 1 : -1;
    const int wph = -shift;
    const size_t arow = (size_t)(m0 >> 11) * CHROW + (m0 & (LSEQ - 1)) + 1 + shift;

    if (tid == 0) {
        for (int s = 0; s < 3; s++) { mbar_init(sb + SM_FULLB + s * 8, 1);
                                      mbar_init(sb + SM_CONSB + s * 8, 8); }
        for (int s = 0; s < 2; s++) { mbar_init(sb + SM_FULLA + s * 8, 1);
                                      mbar_init(sb + SM_CONSA + s * 8, 8); }
    }
    __syncthreads();
    if (tid == 0) {
        issue_A(sb + SA,         sb + SM_FULLA,     in, arow, 0);
        issue_A(sb + SA + 16384, sb + SM_FULLA + 8, in, arow, 1);
        for (int s = 0; s < 3; s++)
            issue_B(sb + SB + s * 16384, sb + SM_FULLB + s * 8, g_W2, n0, s);
    }

    float acc[2][8][4];
#pragma unroll
    for (int i = 0; i < 2; i++)
#pragma unroll
        for (int j = 0; j < 8; j++)
#pragma unroll
            for (int q = 0; q < 4; q++) acc[i][j][q] = 0.0f;

    const bool prod = (wid == 0) && elect_one();
    int bufB = 0, parB = 0;
#pragma unroll 1
    for (int c = 0; c < 8; c++) {
        const int iA = c >> 1, bufA = iA & 1;
        if (!(c & 1)) mbar_wait(sb + SM_FULLA + bufA * 8, (iA >> 1) & 1);
        mbar_wait(sb + SM_FULLB + bufB * 8, parB);
        compute_stage(sb + SA + bufA * 16384, sb + SB + bufB * 16384, c & 1,
                      lane, wm, wn, acc);
        if (elect_one()) mbar_arrive(sb + SM_CONSB + bufB * 8);
        if ((c & 1) && elect_one()) mbar_arrive(sb + SM_CONSA + bufA * 8);
        if (prod) {
            if (c < 5) {
                mbar_wait(sb + SM_CONSB + bufB * 8, parB);
                issue_B(sb + SB + bufB * 16384, sb + SM_FULLB + bufB * 8, g_W2, n0, c + 3);
            }
            if ((c & 1) && c < 4) {                 // c = 1, 3 -> A super-chunk 2, 3
                int scn = (c >> 1) + 2;
                mbar_wait(sb + SM_CONSA + (scn & 1) * 8, 0);
                issue_A(sb + SA + (scn & 1) * 16384, sb + SM_FULLA + (scn & 1) * 8,
                        in, arow, scn);
            }
        }
        if (++bufB == 3) { bufB = 0; parB ^= 1; }
    }

    // epilogue: relu(acc + g_a) -> single fp16, swizzled layout
#pragma unroll
    for (int mt = 0; mt < 2; mt++) {
#pragma unroll
        for (int h = 0; h < 2; h++) {
            int m = m0 + wm * 32 + mt * 16 + (lane >> 2) + h * 8;
            int l = m & (LSEQ - 1);
            size_t rowbase = ((size_t)(m >> 11) * CHROW + l + 1) * 64;
            int ph = ((l + wph) & 7) << 4;
            const float* arow_p = g_a + (size_t)m * DDIM;
#pragma unroll
            for (int nt = 0; nt < 8; nt++) {
                int n = n0 + wn * 64 + nt * 8 + (lane & 3) * 2;
                float2 av = *reinterpret_cast<const float2*>(arow_p + n);
                __half2 hv;
                hv.x = __float2half(fmaxf(acc[mt][nt][2 * h]     + av.x, 0.0f));
                hv.y = __float2half(fmaxf(acc[mt][nt][2 * h + 1] + av.y, 0.0f));
                size_t off = (size_t)(n >> 6) * A_CH_ELEMS + rowbase
                           + ((((n & 63) * 2) ^ ph) >> 1);
                *reinterpret_cast<__half2*>(out + off) = hv;
            }
        }
    }
}

// ---------------------------------------------------------------------------
// final: miu = relu(x@W3^T + b3 + 2*b4 + W4*up[j-1] + W4*down[j+1])
// 16 stages: t<8 up (shift -1), t>=8 down (shift +1). grid (m_tiles, 2).
// ---------------------------------------------------------------------------
__global__ __launch_bounds__(NTHR, 2) void final_kernel(const float* __restrict__ x,
                                                        const float* __restrict__ W3,
                                                        const float* __restrict__ b3,
                                                        const float* __restrict__ b4,
                                                        float* __restrict__ out,
                                                        int src) {
    extern __shared__ char smem[];
    const uint32_t sb = smem_u32(smem);
    const int tid = threadIdx.x, lane = tid & 31, wid = tid >> 5;
    const int wm = wid >> 1, wn = wid & 1;
    const int m0 = blockIdx.x * BM;
    const int n0 = blockIdx.y * BN;
    const size_t rbase = (size_t)(m0 >> 11) * CHROW + (m0 & (LSEQ - 1)) + 1;
    const size_t arow_up = rbase - 1;
    const size_t arow_dn = rbase + 1;
    const __half* upp = g_up[src];
    const __half* dnp = g_dn[src];

    if (tid == 0) {
        for (int s = 0; s < 3; s++) { mbar_init(sb + SM_FULLB + s * 8, 1);
                                      mbar_init(sb + SM_CONSB + s * 8, 8); }
        for (int s = 0; s < 2; s++) { mbar_init(sb + SM_FULLA + s * 8, 1);
                                      mbar_init(sb + SM_CONSA + s * 8, 8); }
    }
    __syncthreads();
    if (tid == 0) {
        issue_A(sb + SA,         sb + SM_FULLA,     upp, arow_up, 0);
        issue_A(sb + SA + 16384, sb + SM_FULLA + 8, upp, arow_up, 1);
        for (int s = 0; s < 3; s++)
            issue_B(sb + SB + s * 16384, sb + SM_FULLB + s * 8, g_W4, n0, s);
    }

    float acc[2][8][4];
#pragma unroll
    for (int i = 0; i < 2; i++)
#pragma unroll
        for (int j = 0; j < 8; j++)
#pragma unroll
            for (int q = 0; q < 4; q++) acc[i][j][q] = 0.0f;

    const bool prod = (wid == 0) && elect_one();
    int bufB = 0, parB = 0;
#pragma unroll 1
    for (int t = 0; t < 16; t++) {
        const int iA = t >> 1, bufA = iA & 1;
        if (!(t & 1)) mbar_wait(sb + SM_FULLA + bufA * 8, (iA >> 1) & 1);
        mbar_wait(sb + SM_FULLB + bufB * 8, parB);
        compute_stage(sb + SA + bufA * 16384, sb + SB + bufB * 16384, t & 1,
                      lane, wm, wn, acc);
        if (elect_one()) mbar_arrive(sb + SM_CONSB + bufB * 8);
        if ((t & 1) && elect_one()) mbar_arrive(sb + SM_CONSA + bufA * 8);
        if (prod) {
            if (t < 13) {
                mbar_wait(sb + SM_CONSB + bufB * 8, parB);
                issue_B(sb + SB + bufB * 16384, sb + SM_FULLB + bufB * 8,
                        g_W4, n0, (t + 3) & 7);
            }
            if ((t & 1) && t < 12) {                // t = 1,3,5,7,9,11 -> iN = 2..7
                int iN = (t >> 1) + 2;
                mbar_wait(sb + SM_CONSA + (iN & 1) * 8, ((iN >> 1) + 1) & 1);
                const __half* arr = (iN >= 4) ? dnp : upp;
                size_t sr = (iN >= 4) ? arow_dn : arow_up;
                issue_A(sb + SA + (iN & 1) * 16384, sb + SM_FULLA + (iN & 1) * 8,
                        arr, sr, iN & 3);
            }
        }
        if (++bufB == 3) { bufB = 0; parB ^= 1; }
    }

    // epilogue: + x@W3^T + b3 + 2*b4, relu, fp32 out
#pragma unroll
    for (int mt = 0; mt < 2; mt++) {
#pragma unroll
        for (int h = 0; h < 2; h++) {
            int m = m0 + wm * 32 + mt * 16 + (lane >> 2) + h * 8;
            int b = m >> 11;
            int l = m & (LSEQ - 1);
            const float* xp = x + (size_t)b * 4 * LSEQ + l;
            float xv[4];
#pragma unroll
            for (int dd = 0; dd < 4; dd++) xv[dd] = xp[dd * LSEQ];
            float* orow = out + (size_t)m * DDIM;
#pragma unroll
            for (int nt = 0; nt < 8; nt++) {
                int n = n0 + wn * 64 + nt * 8 + (lane & 3) * 2;
                float2 b3v = *reinterpret_cast<const float2*>(b3 + n);
                float2 b4v = *reinterpret_cast<const float2*>(b4 + n);
                float v0 = acc[mt][nt][2 * h]     + b3v.x + 2.0f * b4v.x;
                float v1 = acc[mt][nt][2 * h + 1] + b3v.y + 2.0f * b4v.y;
#pragma unroll
                for (int dd = 0; dd < 4; dd++) {
                    v0 = fmaf(xv[dd], W3[n * 4 + dd],       v0);
                    v1 = fmaf(xv[dd], W3[(n + 1) * 4 + dd], v1);
                }
                float2 o = make_float2(fmaxf(v0, 0.0f), fmaxf(v1, 0.0f));
                *reinterpret_cast<float2*>(orow + n) = o;
            }
        }
    }
}

// ---------------------------------------------------------------------------
extern "C" void kernel_launch(void* const* d_in, const int* in_sizes, int n_in,
                              void* d_out, int out_size) {
    const float* x  = (const float*)d_in[0];
    const float* W1 = (const float*)d_in[1];
    const float* b1 = (const float*)d_in[2];
    const float* W2 = (const float*)d_in[3];
    const float* b2 = (const float*)d_in[4];
    const float* W3 = (const float*)d_in[5];
    const float* b3 = (const float*)d_in[6];
    const float* W4 = (const float*)d_in[7];
    const float* b4 = (const float*)d_in[8];
    float* out = (float*)d_out;

    cudaFuncSetAttribute(dp_iter_kernel, cudaFuncAttributeMaxDynamicSharedMemorySize, SMEM_BYTES);
    cudaFuncSetAttribute(final_kernel,   cudaFuncAttributeMaxDynamicSharedMemorySize, SMEM_BYTES);

    int total = MTOT * DDIM;
    prep_kernel<<<(total + 255) / 256, 256>>>(x, W1, b1, b2);
    split_w_kernel<<<(DDIM * DDIM + 255) / 256, 256>>>(W2, W4);

    int src = 0;
    for (int t = 0; t < 7; t++) {
        dp_iter_kernel<<<dim3(MTOT / BM, 2, 2), NTHR, SMEM_BYTES>>>(src);
        src ^= 1;
    }
    final_kernel<<<dim3(MTOT / BM, 2), NTHR, SMEM_BYTES>>>(x, W3, b3, b4, out, src);
}

// round 10
// speedup vs baseline: 4.7391x; 1.2341x over previous
#include <cuda_runtime.h>
#include <cuda_fp16.h>
#include <cstdint>

#define BSZ   16
#define LSEQ  2048
#define DDIM  256
#define MTOT  (BSZ * LSEQ)    // 32768
#define BM    128
#define BN    128
#define NTHR  256

// A (state): single fp16, 4 chunks of k64; row = 64 fp16 = 128B, SW128 phase
// baked per (l + wph). B (weights): single fp16, 4 chunks of k64, row = 64
// fp16 = 128B, phase (n&7).
#define CHROW  2056
#define A_CH_ELEMS ((size_t)BSZ * CHROW * 64)   // per k64 chunk
#define W_CH   (256 * 64)                        // per k64 weight chunk

// ---------------- global state (static .bss; pad rows stay zero) ----------
__device__ __align__(128) float  g_a[MTOT * DDIM];              // a + b2 folded
__device__ __align__(128) __half g_up[2][4 * A_CH_ELEMS];
__device__ __align__(128) __half g_dn[2][4 * A_CH_ELEMS];
__device__ __align__(128) __half g_W2[4 * W_CH];
__device__ __align__(128) __half g_W4[4 * W_CH];

// ---------------- helpers ----------------
__device__ __forceinline__ uint32_t smem_u32(const void* p) {
    uint32_t a;
    asm("{ .reg .u64 t; cvta.to.shared.u64 t, %1; cvt.u32.u64 %0, t; }" : "=r"(a) : "l"(p));
    return a;
}
__device__ __forceinline__ uint32_t elect_one() {
    uint32_t pred;
    asm volatile("{\n\t.reg .pred p;\n\telect.sync _|p, 0xFFFFFFFF;\n\t"
                 "selp.b32 %0, 1, 0, p;\n\t}" : "=r"(pred));
    return pred;
}
__device__ __forceinline__ void ldm_x4(uint32_t* r, uint32_t addr) {
    asm volatile("ldmatrix.sync.aligned.m8n8.x4.shared.b16 {%0,%1,%2,%3}, [%4];"
                 : "=r"(r[0]), "=r"(r[1]), "=r"(r[2]), "=r"(r[3]) : "r"(addr));
}
__device__ __forceinline__ void mma_f16(float* c, const uint32_t* a, uint32_t b0, uint32_t b1) {
    asm volatile("mma.sync.aligned.m16n8k16.row.col.f32.f16.f16.f32 "
                 "{%0,%1,%2,%3}, {%4,%5,%6,%7}, {%8,%9}, {%0,%1,%2,%3};"
                 : "+f"(c[0]), "+f"(c[1]), "+f"(c[2]), "+f"(c[3])
                 : "r"(a[0]), "r"(a[1]), "r"(a[2]), "r"(a[3]), "r"(b0), "r"(b1));
}
__device__ __forceinline__ void bulk_g2s(uint32_t sdst, const void* gsrc,
                                         uint32_t bytes, uint32_t mbar) {
    asm volatile(
        "cp.async.bulk.shared::cluster.global.mbarrier::complete_tx::bytes [%0], [%1], %2, [%3];"
        :: "r"(sdst), "l"(gsrc), "r"(bytes), "r"(mbar) : "memory");
}
__device__ __forceinline__ void mbar_init(uint32_t mbar, uint32_t cnt) {
    asm volatile("mbarrier.init.shared.b64 [%0], %1;" :: "r"(mbar), "r"(cnt) : "memory");
}
__device__ __forceinline__ void mbar_expect_tx(uint32_t mbar, uint32_t bytes) {
    asm volatile("mbarrier.arrive.expect_tx.shared.b64 _, [%0], %1;"
                 :: "r"(mbar), "r"(bytes) : "memory");
}
__device__ __forceinline__ void mbar_arrive(uint32_t mbar) {
    asm volatile("mbarrier.arrive.release.cta.shared::cta.b64 _, [%0];"
                 :: "r"(mbar) : "memory");
}
__device__ __forceinline__ void mbar_wait(uint32_t mbar, uint32_t parity) {
    uint32_t done;
    asm volatile(
        "{\n\t.reg .pred p;\n\t"
        "mbarrier.try_wait.parity.acquire.cta.shared::cta.b64 p, [%1], %2;\n\t"
        "selp.b32 %0, 1, 0, p;\n\t}"
        : "=r"(done) : "r"(mbar), "r"(parity) : "memory");
    if (!done) {
        asm volatile(
            "{\n\t.reg .pred P1;\n\t"
            "W_%=:\n\t"
            "mbarrier.try_wait.parity.acquire.cta.shared::cta.b64 P1, [%0], %1, 0x989680;\n\t"
            "@P1 bra.uni D_%=;\n\t"
            "bra.uni W_%=;\n\t"
            "D_%=:\n\t}"
            :: "r"(mbar), "r"(parity) : "memory");
    }
}

// ---------------- SMEM layout: 3 stages of {A 16KB, B 16KB} ----------------
static constexpr int SA      = 0;
static constexpr int SB      = 16384;
static constexpr int STAGE   = 32768;
static constexpr int NSTAGE  = 3;
static constexpr int SM_FULL = NSTAGE * STAGE;            // 98304
static constexpr int SM_CONS = SM_FULL + NSTAGE * 8;
static constexpr int SMEM_BYTES = SM_CONS + NSTAGE * 8;
static constexpr uint32_t STAGE_TX = 2 * 16384;

// state element index (fp16 units) for (m, n), write-phase wph
__device__ __forceinline__ size_t st_idx(int m, int n, int wph) {
    int l = m & (LSEQ - 1);
    size_t row = (size_t)(m >> 11) * CHROW + l + 1;
    int ph  = ((l + wph) & 7) << 4;
    int raw = (n & 63) * 2;
    return (size_t)(n >> 6) * A_CH_ELEMS + row * 64 + ((raw ^ ph) >> 1);
}

// ---------------------------------------------------------------------------
__global__ void prep_kernel(const float* __restrict__ x,
                            const float* __restrict__ W1,
                            const float* __restrict__ b1,
                            const float* __restrict__ b2) {
    int idx = blockIdx.x * blockDim.x + threadIdx.x;
    if (idx >= MTOT * DDIM) return;
    int n = idx & (DDIM - 1);
    int m = idx >> 8;
    int b = m / LSEQ;
    int l = m & (LSEQ - 1);
    const float* xp = x + (size_t)b * 4 * LSEQ + l;
    float s = b1[n] + b2[n];
#pragma unroll
    for (int dd = 0; dd < 4; dd++)
        s = fmaf(xp[dd * LSEQ], W1[n * 4 + dd], s);
    g_a[idx] = s;
    __half h = __float2half(fmaxf(s, 0.0f));
    g_up[0][st_idx(m, n, +1)] = h;
    g_dn[0][st_idx(m, n, -1)] = h;
}

// split W2/W4 into single-fp16 chunk-major (k64) swizzled layout
__global__ void split_w_kernel(const float* __restrict__ W2,
                               const float* __restrict__ W4) {
    int idx = blockIdx.x * blockDim.x + threadIdx.x;   // (n, k)
    if (idx >= DDIM * DDIM) return;
    int n = idx >> 8, k = idx & 255;
    int ph = (n & 7) << 4;
    size_t off = (size_t)(k >> 6) * W_CH + (size_t)n * 64 + ((((k & 63) * 2)) ^ ph) / 2;
    g_W2[off] = __float2half(W2[idx]);
    g_W4[off] = __float2half(W4[idx]);
}

// one stage = A chunk + B chunk (k64), single thread
__device__ __forceinline__ void issue_stage(uint32_t sbase, uint32_t mbar,
                                            const __half* in, const __half* w,
                                            size_t arow, int n0, int c) {
    mbar_expect_tx(mbar, STAGE_TX);
    bulk_g2s(sbase + SA, in + (size_t)c * A_CH_ELEMS + arow * 64, 16384, mbar);
    bulk_g2s(sbase + SB, w + (size_t)c * W_CH + (size_t)n0 * 64, 16384, mbar);
}

// compute one k64 stage, single-pass fp16. warp tile 32x64.
// Per ks (k16): each acc quad is hit exactly once -> RAW distance = 16 MMAs.
__device__ __forceinline__ void compute_stage(uint32_t base, int lane, int wm, int wn,
                                              float acc[2][8][4]) {
    const uint32_t swz  = (uint32_t)(lane & 7) << 4;
    const uint32_t rlo  = (uint32_t)(lane & 15);
    const uint32_t hi16 = (uint32_t)(lane >> 4) * 16;
#pragma unroll
    for (int ks = 0; ks < 4; ks++) {
        uint32_t ch = ((uint32_t)(ks * 32) + hi16) ^ swz;
        uint32_t ah[2][4];
#pragma unroll
        for (int mt = 0; mt < 2; mt++)
            ldm_x4(ah[mt], base + SA + (wm * 32 + mt * 16 + rlo) * 128 + ch);
        uint32_t bf[4][4];
#pragma unroll
        for (int pr = 0; pr < 4; pr++)
            ldm_x4(bf[pr], base + SB + ((wn * 4 + pr) * 16 + rlo) * 128 + ch);
#pragma unroll
        for (int pr = 0; pr < 4; pr++)
#pragma unroll
            for (int mt = 0; mt < 2; mt++) {
                mma_f16(acc[mt][pr * 2],     ah[mt], bf[pr][0], bf[pr][2]);
                mma_f16(acc[mt][pr * 2 + 1], ah[mt], bf[pr][1], bf[pr][3]);
            }
    }
}

// ---------------------------------------------------------------------------
// DP iteration: out = relu(g_a + shift(in)@W2^T). grid (m_tiles, 2, 2 lanes).
// 4 stages of k64; 3-deep ring.
// ---------------------------------------------------------------------------
__global__ __launch_bounds__(NTHR, 2) void dp_iter_kernel(int src) {
    extern __shared__ char smem[];
    const uint32_t sb = smem_u32(smem);
    const int tid = threadIdx.x, lane = tid & 31, wid = tid >> 5;
    const int wm = wid >> 1, wn = wid & 1;
    const int m0 = blockIdx.x * BM;
    const int n0 = blockIdx.y * BN;
    const int ln = blockIdx.z;

    const __half* in  = ln ? g_dn[src]     : g_up[src];
    __half*       out = ln ? g_dn[src ^ 1] : g_up[src ^ 1];
    const int shift = ln ? 1 : -1;
    const int wph = -shift;
    const size_t arow = (size_t)(m0 >> 11) * CHROW + (m0 & (LSEQ - 1)) + 1 + shift;

    if (tid == 0) {
        for (int s = 0; s < NSTAGE; s++) {
            mbar_init(sb + SM_FULL + s * 8, 1);
            mbar_init(sb + SM_CONS + s * 8, 8);
        }
    }
    __syncthreads();
    if (tid == 0)
        for (int s = 0; s < NSTAGE; s++)
            issue_stage(sb + s * STAGE, sb + SM_FULL + s * 8, in, g_W2, arow, n0, s);

    float acc[2][8][4];
#pragma unroll
    for (int i = 0; i < 2; i++)
#pragma unroll
        for (int j = 0; j < 8; j++)
#pragma unroll
            for (int q = 0; q < 4; q++) acc[i][j][q] = 0.0f;

    const bool prod = (wid == 0) && elect_one();
    int buf = 0, par = 0;
#pragma unroll 1
    for (int c = 0; c < 4; c++) {
        mbar_wait(sb + SM_FULL + buf * 8, par);
        compute_stage(sb + buf * STAGE, lane, wm, wn, acc);
        if (elect_one()) mbar_arrive(sb + SM_CONS + buf * 8);
        if (c < 1 && prod) {
            mbar_wait(sb + SM_CONS + buf * 8, par);
            issue_stage(sb + buf * STAGE, sb + SM_FULL + buf * 8, in, g_W2, arow, n0, c + 3);
        }
        if (++buf == NSTAGE) { buf = 0; par ^= 1; }
    }

    // epilogue: relu(acc + g_a) -> single fp16, swizzled layout
#pragma unroll
    for (int mt = 0; mt < 2; mt++) {
#pragma unroll
        for (int h = 0; h < 2; h++) {
            int m = m0 + wm * 32 + mt * 16 + (lane >> 2) + h * 8;
            int l = m & (LSEQ - 1);
            size_t rowbase = ((size_t)(m >> 11) * CHROW + l + 1) * 64;
            int ph = ((l + wph) & 7) << 4;
            const float* arow_p = g_a + (size_t)m * DDIM;
#pragma unroll
            for (int nt = 0; nt < 8; nt++) {
                int n = n0 + wn * 64 + nt * 8 + (lane & 3) * 2;
                float2 av = *reinterpret_cast<const float2*>(arow_p + n);
                __half2 hv;
                hv.x = __float2half(fmaxf(acc[mt][nt][2 * h]     + av.x, 0.0f));
                hv.y = __float2half(fmaxf(acc[mt][nt][2 * h + 1] + av.y, 0.0f));
                size_t off = (size_t)(n >> 6) * A_CH_ELEMS + rowbase
                           + ((((n & 63) * 2) ^ ph) >> 1);
                *reinterpret_cast<__half2*>(out + off) = hv;
            }
        }
    }
}

// ---------------------------------------------------------------------------
// final: miu = relu(x@W3^T + b3 + 2*b4 + W4*up[j-1] + W4*down[j+1])
// 8 stages: t<4 up (shift -1), t>=4 down (shift +1). grid (m_tiles, 2).
// ---------------------------------------------------------------------------
__global__ __launch_bounds__(NTHR, 2) void final_kernel(const float* __restrict__ x,
                                                        const float* __restrict__ W3,
                                                        const float* __restrict__ b3,
                                                        const float* __restrict__ b4,
                                                        float* __restrict__ out,
                                                        int src) {
    extern __shared__ char smem[];
    const uint32_t sb = smem_u32(smem);
    const int tid = threadIdx.x, lane = tid & 31, wid = tid >> 5;
    const int wm = wid >> 1, wn = wid & 1;
    const int m0 = blockIdx.x * BM;
    const int n0 = blockIdx.y * BN;
    const size_t rbase = (size_t)(m0 >> 11) * CHROW + (m0 & (LSEQ - 1)) + 1;
    const size_t arow_up = rbase - 1;
    const size_t arow_dn = rbase + 1;
    const __half* upp = g_up[src];
    const __half* dnp = g_dn[src];

    if (tid == 0) {
        for (int s = 0; s < NSTAGE; s++) {
            mbar_init(sb + SM_FULL + s * 8, 1);
            mbar_init(sb + SM_CONS + s * 8, 8);
        }
    }
    __syncthreads();
    if (tid == 0)
        for (int s = 0; s < NSTAGE; s++)
            issue_stage(sb + s * STAGE, sb + SM_FULL + s * 8, upp, g_W4, arow_up, n0, s);

    float acc[2][8][4];
#pragma unroll
    for (int i = 0; i < 2; i++)
#pragma unroll
        for (int j = 0; j < 8; j++)
#pragma unroll
            for (int q = 0; q < 4; q++) acc[i][j][q] = 0.0f;

    const bool prod = (wid == 0) && elect_one();
    int buf = 0, par = 0;
#pragma unroll 1
    for (int t = 0; t < 8; t++) {
        mbar_wait(sb + SM_FULL + buf * 8, par);
        compute_stage(sb + buf * STAGE, lane, wm, wn, acc);
        if (elect_one()) mbar_arrive(sb + SM_CONS + buf * 8);
        if (t < 5 && prod) {
            mbar_wait(sb + SM_CONS + buf * 8, par);
            int tn = t + 3;
            int phx = tn >> 2;
            issue_stage(sb + buf * STAGE, sb + SM_FULL + buf * 8,
                        phx ? dnp : upp, g_W4,
                        phx ? arow_dn : arow_up, n0, tn & 3);
        }
        if (++buf == NSTAGE) { buf = 0; par ^= 1; }
    }

    // epilogue: + x@W3^T + b3 + 2*b4, relu, fp32 out
#pragma unroll
    for (int mt = 0; mt < 2; mt++) {
#pragma unroll
        for (int h = 0; h < 2; h++) {
            int m = m0 + wm * 32 + mt * 16 + (lane >> 2) + h * 8;
            int b = m >> 11;
            int l = m & (LSEQ - 1);
            const float* xp = x + (size_t)b * 4 * LSEQ + l;
            float xv[4];
#pragma unroll
            for (int dd = 0; dd < 4; dd++) xv[dd] = xp[dd * LSEQ];
            float* orow = out + (size_t)m * DDIM;
#pragma unroll
            for (int nt = 0; nt < 8; nt++) {
                int n = n0 + wn * 64 + nt * 8 + (lane & 3) * 2;
                float2 b3v = *reinterpret_cast<const float2*>(b3 + n);
                float2 b4v = *reinterpret_cast<const float2*>(b4 + n);
                float v0 = acc[mt][nt][2 * h]     + b3v.x + 2.0f * b4v.x;
                float v1 = acc[mt][nt][2 * h + 1] + b3v.y + 2.0f * b4v.y;
#pragma unroll
                for (int dd = 0; dd < 4; dd++) {
                    v0 = fmaf(xv[dd], W3[n * 4 + dd],       v0);
                    v1 = fmaf(xv[dd], W3[(n + 1) * 4 + dd], v1);
                }
                float2 o = make_float2(fmaxf(v0, 0.0f), fmaxf(v1, 0.0f));
                *reinterpret_cast<float2*>(orow + n) = o;
            }
        }
    }
}

// ---------------------------------------------------------------------------
extern "C" void kernel_launch(void* const* d_in, const int* in_sizes, int n_in,
                              void* d_out, int out_size) {
    const float* x  = (const float*)d_in[0];
    const float* W1 = (const float*)d_in[1];
    const float* b1 = (const float*)d_in[2];
    const float* W2 = (const float*)d_in[3];
    const float* b2 = (const float*)d_in[4];
    const float* W3 = (const float*)d_in[5];
    const float* b3 = (const float*)d_in[6];
    const float* W4 = (const float*)d_in[7];
    const float* b4 = (const float*)d_in[8];
    float* out = (float*)d_out;

    cudaFuncSetAttribute(dp_iter_kernel, cudaFuncAttributeMaxDynamicSharedMemorySize, SMEM_BYTES);
    cudaFuncSetAttribute(final_kernel,   cudaFuncAttributeMaxDynamicSharedMemorySize, SMEM_BYTES);

    int total = MTOT * DDIM;
    prep_kernel<<<(total + 255) / 256, 256>>>(x, W1, b1, b2);
    split_w_kernel<<<(DDIM * DDIM + 255) / 256, 256>>>(W2, W4);

    int src = 0;
    for (int t = 0; t < 7; t++) {
        dp_iter_kernel<<<dim3(MTOT / BM, 2, 2), NTHR, SMEM_BYTES>>>(src);
        src ^= 1;
    }
    final_kernel<<<dim3(MTOT / BM, 2), NTHR, SMEM_BYTES>>>(x, W3, b3, b4, out, src);
}

// round 11
// speedup vs baseline: 7.6135x; 1.6065x over previous
#include <cuda_runtime.h>
#include <cuda_fp16.h>
#include <cstdint>

#define BSZ   16
#define LSEQ  2048
#define DDIM  256
#define MTOT  (BSZ * LSEQ)    // 32768
#define BM    128
#define BN    128
#define NTHR  256

// A (state): single fp16, 4 chunks of k64; row = 64 fp16 = 128B, SW128 phase
// baked per (l + wph). B (weights): single fp16, 4 chunks of k64, phase (n&7).
// ext: rank-5 tail [x | 1] * [W | bias], rows of 16 fp16 = 32B, unswizzled.
#define CHROW  2056
#define A_CH_ELEMS ((size_t)BSZ * CHROW * 64)   // per k64 chunk
#define W_CH   (256 * 64)

// ---------------- global state (static .bss; pad rows stay zero) ----------
__device__ __align__(128) __half g_up[2][4 * A_CH_ELEMS];
__device__ __align__(128) __half g_dn[2][4 * A_CH_ELEMS];
__device__ __align__(128) __half g_W2[4 * W_CH];
__device__ __align__(128) __half g_W4[4 * W_CH];
__device__ __align__(128) __half g_xe[(size_t)MTOT * 16];   // [x0..x3, 1, 0...]
__device__ __align__(128) __half g_w2e[256 * 16];           // [W1, b1+b2, 0...]
__device__ __align__(128) __half g_w4e[256 * 16];           // [W3, b3+2b4, 0...]

// ---------------- helpers ----------------
__device__ __forceinline__ uint32_t smem_u32(const void* p) {
    uint32_t a;
    asm("{ .reg .u64 t; cvta.to.shared.u64 t, %1; cvt.u32.u64 %0, t; }" : "=r"(a) : "l"(p));
    return a;
}
__device__ __forceinline__ uint32_t elect_one() {
    uint32_t pred;
    asm volatile("{\n\t.reg .pred p;\n\telect.sync _|p, 0xFFFFFFFF;\n\t"
                 "selp.b32 %0, 1, 0, p;\n\t}" : "=r"(pred));
    return pred;
}
__device__ __forceinline__ void ldm_x4(uint32_t* r, uint32_t addr) {
    asm volatile("ldmatrix.sync.aligned.m8n8.x4.shared.b16 {%0,%1,%2,%3}, [%4];"
                 : "=r"(r[0]), "=r"(r[1]), "=r"(r[2]), "=r"(r[3]) : "r"(addr));
}
__device__ __forceinline__ void mma_f16(float* c, const uint32_t* a, uint32_t b0, uint32_t b1) {
    asm volatile("mma.sync.aligned.m16n8k16.row.col.f32.f16.f16.f32 "
                 "{%0,%1,%2,%3}, {%4,%5,%6,%7}, {%8,%9}, {%0,%1,%2,%3};"
                 : "+f"(c[0]), "+f"(c[1]), "+f"(c[2]), "+f"(c[3])
                 : "r"(a[0]), "r"(a[1]), "r"(a[2]), "r"(a[3]), "r"(b0), "r"(b1));
}
__device__ __forceinline__ void bulk_g2s(uint32_t sdst, const void* gsrc,
                                         uint32_t bytes, uint32_t mbar) {
    asm volatile(
        "cp.async.bulk.shared::cluster.global.mbarrier::complete_tx::bytes [%0], [%1], %2, [%3];"
        :: "r"(sdst), "l"(gsrc), "r"(bytes), "r"(mbar) : "memory");
}
__device__ __forceinline__ void mbar_init(uint32_t mbar, uint32_t cnt) {
    asm volatile("mbarrier.init.shared.b64 [%0], %1;" :: "r"(mbar), "r"(cnt) : "memory");
}
__device__ __forceinline__ void mbar_expect_tx(uint32_t mbar, uint32_t bytes) {
    asm volatile("mbarrier.arrive.expect_tx.shared.b64 _, [%0], %1;"
                 :: "r"(mbar), "r"(bytes) : "memory");
}
__device__ __forceinline__ void mbar_arrive(uint32_t mbar) {
    asm volatile("mbarrier.arrive.release.cta.shared::cta.b64 _, [%0];"
                 :: "r"(mbar) : "memory");
}
__device__ __forceinline__ void mbar_wait(uint32_t mbar, uint32_t parity) {
    uint32_t done;
    asm volatile(
        "{\n\t.reg .pred p;\n\t"
        "mbarrier.try_wait.parity.acquire.cta.shared::cta.b64 p, [%1], %2;\n\t"
        "selp.b32 %0, 1, 0, p;\n\t}"
        : "=r"(done) : "r"(mbar), "r"(parity) : "memory");
    if (!done) {
        asm volatile(
            "{\n\t.reg .pred P1;\n\t"
            "W_%=:\n\t"
            "mbarrier.try_wait.parity.acquire.cta.shared::cta.b64 P1, [%0], %1, 0x989680;\n\t"
            "@P1 bra.uni D_%=;\n\t"
            "bra.uni W_%=;\n\t"
            "D_%=:\n\t}"
            :: "r"(mbar), "r"(parity) : "memory");
    }
}

// ---------------- SMEM layout ----------------
static constexpr int SA      = 0;
static constexpr int SB      = 16384;
static constexpr int STAGE   = 32768;
static constexpr int NSTAGE  = 3;
static constexpr int SXE     = NSTAGE * STAGE;            // 98304, A ext 4KB
static constexpr int SWE     = SXE + 4096;                // B ext 4KB
static constexpr int SM_FULL = SWE + 4096;                // 106496
static constexpr int SM_CONS = SM_FULL + NSTAGE * 8;
static constexpr int SM_EXTF = SM_CONS + NSTAGE * 8;
static constexpr int SMEM_BYTES = SM_EXTF + 8;
static constexpr uint32_t STAGE_TX = 2 * 16384;

// state element index (fp16 units) for (m, n), write-phase wph
__device__ __forceinline__ size_t st_idx(int m, int n, int wph) {
    int l = m & (LSEQ - 1);
    size_t row = (size_t)(m >> 11) * CHROW + l + 1;
    int ph  = ((l + wph) & 7) << 4;
    int raw = (n & 63) * 2;
    return (size_t)(n >> 6) * A_CH_ELEMS + row * 64 + ((raw ^ ph) >> 1);
}

// ---------------------------------------------------------------------------
// prep: state#1 = relu(x@W1^T + b1 + b2) -> fp16 swizzled state (no g_a)
// ---------------------------------------------------------------------------
__global__ void prep_kernel(const float* __restrict__ x,
                            const float* __restrict__ W1,
                            const float* __restrict__ b1,
                            const float* __restrict__ b2) {
    int idx = blockIdx.x * blockDim.x + threadIdx.x;
    if (idx >= MTOT * DDIM) return;
    int n = idx & (DDIM - 1);
    int m = idx >> 8;
    int b = m / LSEQ;
    int l = m & (LSEQ - 1);
    const float* xp = x + (size_t)b * 4 * LSEQ + l;
    float s = b1[n] + b2[n];
#pragma unroll
    for (int dd = 0; dd < 4; dd++)
        s = fmaf(xp[dd * LSEQ], W1[n * 4 + dd], s);
    __half h = __float2half(fmaxf(s, 0.0f));
    g_up[0][st_idx(m, n, +1)] = h;
    g_dn[0][st_idx(m, n, -1)] = h;
}

// build x_ext rows: [x0..x3, 1, 0...] per m, 16 fp16 = 32B
__global__ void xext_kernel(const float* __restrict__ x) {
    int m = blockIdx.x * blockDim.x + threadIdx.x;
    if (m >= MTOT) return;
    int b = m >> 11, l = m & (LSEQ - 1);
    __half r[16];
#pragma unroll
    for (int j = 0; j < 16; j++) r[j] = __float2half(0.0f);
#pragma unroll
    for (int dd = 0; dd < 4; dd++)
        r[dd] = __float2half(x[(size_t)b * 4 * LSEQ + dd * LSEQ + l]);
    r[4] = __float2half(1.0f);
    uint4* dst = reinterpret_cast<uint4*>(g_xe + (size_t)m * 16);
    dst[0] = reinterpret_cast<const uint4*>(r)[0];
    dst[1] = reinterpret_cast<const uint4*>(r)[1];
}

// split W2/W4 into fp16 chunk-major swizzled layout + ext rows
__global__ void split_w_kernel(const float* __restrict__ W2,
                               const float* __restrict__ W4,
                               const float* __restrict__ W1,
                               const float* __restrict__ b1,
                               const float* __restrict__ b2,
                               const float* __restrict__ W3,
                               const float* __restrict__ b3,
                               const float* __restrict__ b4) {
    int idx = blockIdx.x * blockDim.x + threadIdx.x;   // (n, k)
    if (idx >= DDIM * DDIM) return;
    int n = idx >> 8, k = idx & 255;
    int ph = (n & 7) << 4;
    size_t off = (size_t)(k >> 6) * W_CH + (size_t)n * 64 + ((((k & 63) * 2)) ^ ph) / 2;
    g_W2[off] = __float2half(W2[idx]);
    g_W4[off] = __float2half(W4[idx]);
    if (k == 0) {
        __half r2[16], r4[16];
#pragma unroll
        for (int j = 0; j < 16; j++) { r2[j] = __float2half(0.0f); r4[j] = r2[j]; }
#pragma unroll
        for (int dd = 0; dd < 4; dd++) {
            r2[dd] = __float2half(W1[n * 4 + dd]);
            r4[dd] = __float2half(W3[n * 4 + dd]);
        }
        r2[4] = __float2half(b1[n] + b2[n]);
        r4[4] = __float2half(b3[n] + 2.0f * b4[n]);
        uint4* d2 = reinterpret_cast<uint4*>(g_w2e + (size_t)n * 16);
        uint4* d4 = reinterpret_cast<uint4*>(g_w4e + (size_t)n * 16);
        d2[0] = reinterpret_cast<const uint4*>(r2)[0];
        d2[1] = reinterpret_cast<const uint4*>(r2)[1];
        d4[0] = reinterpret_cast<const uint4*>(r4)[0];
        d4[1] = reinterpret_cast<const uint4*>(r4)[1];
    }
}

// one stage = A chunk + B chunk (k64), single thread
__device__ __forceinline__ void issue_stage(uint32_t sbase, uint32_t mbar,
                                            const __half* in, const __half* w,
                                            size_t arow, int n0, int c) {
    mbar_expect_tx(mbar, STAGE_TX);
    bulk_g2s(sbase + SA, in + (size_t)c * A_CH_ELEMS + arow * 64, 16384, mbar);
    bulk_g2s(sbase + SB, w + (size_t)c * W_CH + (size_t)n0 * 64, 16384, mbar);
}
// ext pair: x rows + weight-ext rows (4KB each)
__device__ __forceinline__ void issue_ext(uint32_t sb, uint32_t mbar,
                                          const __half* we, int m0, int n0) {
    mbar_expect_tx(mbar, 8192);
    bulk_g2s(sb + SXE, g_xe + (size_t)m0 * 16, 4096, mbar);
    bulk_g2s(sb + SWE, we + (size_t)n0 * 16, 4096, mbar);
}

// compute one k64 stage, single-pass fp16. warp tile 32x64.
__device__ __forceinline__ void compute_stage(uint32_t base, int lane, int wm, int wn,
                                              float acc[2][8][4]) {
    const uint32_t swz  = (uint32_t)(lane & 7) << 4;
    const uint32_t rlo  = (uint32_t)(lane & 15);
    const uint32_t hi16 = (uint32_t)(lane >> 4) * 16;
#pragma unroll
    for (int ks = 0; ks < 4; ks++) {
        uint32_t ch = ((uint32_t)(ks * 32) + hi16) ^ swz;
        uint32_t ah[2][4];
#pragma unroll
        for (int mt = 0; mt < 2; mt++)
            ldm_x4(ah[mt], base + SA + (wm * 32 + mt * 16 + rlo) * 128 + ch);
        uint32_t bf[4][4];
#pragma unroll
        for (int pr = 0; pr < 4; pr++)
            ldm_x4(bf[pr], base + SB + ((wn * 4 + pr) * 16 + rlo) * 128 + ch);
#pragma unroll
        for (int pr = 0; pr < 4; pr++)
#pragma unroll
            for (int mt = 0; mt < 2; mt++) {
                mma_f16(acc[mt][pr * 2],     ah[mt], bf[pr][0], bf[pr][2]);
                mma_f16(acc[mt][pr * 2 + 1], ah[mt], bf[pr][1], bf[pr][3]);
            }
    }
}

// ext k16 step: rows of 32B, unswizzled (conflict-free: 16 rows x 32B = 512B)
__device__ __forceinline__ void compute_ext(uint32_t sb, int lane, int wm, int wn,
                                            float acc[2][8][4]) {
    const uint32_t rlo  = (uint32_t)(lane & 15);
    const uint32_t hi16 = (uint32_t)(lane >> 4) * 16;
    uint32_t ah[2][4];
#pragma unroll
    for (int mt = 0; mt < 2; mt++)
        ldm_x4(ah[mt], sb + SXE + (wm * 32 + mt * 16 + rlo) * 32 + hi16);
    uint32_t bf[4][4];
#pragma unroll
    for (int pr = 0; pr < 4; pr++)
        ldm_x4(bf[pr], sb + SWE + ((wn * 4 + pr) * 16 + rlo) * 32 + hi16);
#pragma unroll
    for (int pr = 0; pr < 4; pr++)
#pragma unroll
        for (int mt = 0; mt < 2; mt++) {
            mma_f16(acc[mt][pr * 2],     ah[mt], bf[pr][0], bf[pr][2]);
            mma_f16(acc[mt][pr * 2 + 1], ah[mt], bf[pr][1], bf[pr][3]);
        }
}

// ---------------------------------------------------------------------------
// DP iteration: out = relu(shift(in)@W2^T + x@W1^T + b1 + b2) — fully fused.
// ---------------------------------------------------------------------------
__global__ __launch_bounds__(NTHR, 2) void dp_iter_kernel(int src) {
    extern __shared__ char smem[];
    const uint32_t sb = smem_u32(smem);
    const int tid = threadIdx.x, lane = tid & 31, wid = tid >> 5;
    const int wm = wid >> 1, wn = wid & 1;
    const int m0 = blockIdx.x * BM;
    const int n0 = blockIdx.y * BN;
    const int ln = blockIdx.z;

    const __half* in  = ln ? g_dn[src]     : g_up[src];
    __half*       out = ln ? g_dn[src ^ 1] : g_up[src ^ 1];
    const int shift = ln ? 1 : -1;
    const int wph = -shift;
    const size_t arow = (size_t)(m0 >> 11) * CHROW + (m0 & (LSEQ - 1)) + 1 + shift;

    if (tid == 0) {
        for (int s = 0; s < NSTAGE; s++) {
            mbar_init(sb + SM_FULL + s * 8, 1);
            mbar_init(sb + SM_CONS + s * 8, 8);
        }
        mbar_init(sb + SM_EXTF, 1);
    }
    __syncthreads();
    if (tid == 0) {
        issue_ext(sb, sb + SM_EXTF, g_w2e, m0, n0);
        for (int s = 0; s < NSTAGE; s++)
            issue_stage(sb + s * STAGE, sb + SM_FULL + s * 8, in, g_W2, arow, n0, s);
    }

    float acc[2][8][4];
#pragma unroll
    for (int i = 0; i < 2; i++)
#pragma unroll
        for (int j = 0; j < 8; j++)
#pragma unroll
            for (int q = 0; q < 4; q++) acc[i][j][q] = 0.0f;

    const bool prod = (wid == 0) && elect_one();
    int buf = 0, par = 0;
#pragma unroll 1
    for (int c = 0; c < 4; c++) {
        mbar_wait(sb + SM_FULL + buf * 8, par);
        compute_stage(sb + buf * STAGE, lane, wm, wn, acc);
        if (elect_one()) mbar_arrive(sb + SM_CONS + buf * 8);
        if (c < 1 && prod) {
            mbar_wait(sb + SM_CONS + buf * 8, par);
            issue_stage(sb + buf * STAGE, sb + SM_FULL + buf * 8, in, g_W2, arow, n0, c + 3);
        }
        if (++buf == NSTAGE) { buf = 0; par ^= 1; }
    }
    mbar_wait(sb + SM_EXTF, 0);
    compute_ext(sb, lane, wm, wn, acc);

    // epilogue: relu(acc) -> fp16 state, swizzled layout (no global reads!)
#pragma unroll
    for (int mt = 0; mt < 2; mt++) {
#pragma unroll
        for (int h = 0; h < 2; h++) {
            int m = m0 + wm * 32 + mt * 16 + (lane >> 2) + h * 8;
            int l = m & (LSEQ - 1);
            size_t rowbase = ((size_t)(m >> 11) * CHROW + l + 1) * 64;
            int ph = ((l + wph) & 7) << 4;
#pragma unroll
            for (int nt = 0; nt < 8; nt++) {
                int n = n0 + wn * 64 + nt * 8 + (lane & 3) * 2;
                __half2 hv;
                hv.x = __float2half(fmaxf(acc[mt][nt][2 * h],     0.0f));
                hv.y = __float2half(fmaxf(acc[mt][nt][2 * h + 1], 0.0f));
                size_t off = (size_t)(n >> 6) * A_CH_ELEMS + rowbase
                           + ((((n & 63) * 2) ^ ph) >> 1);
                *reinterpret_cast<__half2*>(out + off) = hv;
            }
        }
    }
}

// ---------------------------------------------------------------------------
// final: miu = relu(x@W3^T + b3 + 2*b4 + W4*up[j-1] + W4*down[j+1])
// 8 stages (up then down) + ext. grid (m_tiles, 2).
// ---------------------------------------------------------------------------
__global__ __launch_bounds__(NTHR, 2) void final_kernel(float* __restrict__ out,
                                                        int src) {
    extern __shared__ char smem[];
    const uint32_t sb = smem_u32(smem);
    const int tid = threadIdx.x, lane = tid & 31, wid = tid >> 5;
    const int wm = wid >> 1, wn = wid & 1;
    const int m0 = blockIdx.x * BM;
    const int n0 = blockIdx.y * BN;
    const size_t rbase = (size_t)(m0 >> 11) * CHROW + (m0 & (LSEQ - 1)) + 1;
    const size_t arow_up = rbase - 1;
    const size_t arow_dn = rbase + 1;
    const __half* upp = g_up[src];
    const __half* dnp = g_dn[src];

    if (tid == 0) {
        for (int s = 0; s < NSTAGE; s++) {
            mbar_init(sb + SM_FULL + s * 8, 1);
            mbar_init(sb + SM_CONS + s * 8, 8);
        }
        mbar_init(sb + SM_EXTF, 1);
    }
    __syncthreads();
    if (tid == 0) {
        issue_ext(sb, sb + SM_EXTF, g_w4e, m0, n0);
        for (int s = 0; s < NSTAGE; s++)
            issue_stage(sb + s * STAGE, sb + SM_FULL + s * 8, upp, g_W4, arow_up, n0, s);
    }

    float acc[2][8][4];
#pragma unroll
    for (int i = 0; i < 2; i++)
#pragma unroll
        for (int j = 0; j < 8; j++)
#pragma unroll
            for (int q = 0; q < 4; q++) acc[i][j][q] = 0.0f;

    const bool prod = (wid == 0) && elect_one();
    int buf = 0, par = 0;
#pragma unroll 1
    for (int t = 0; t < 8; t++) {
        mbar_wait(sb + SM_FULL + buf * 8, par);
        compute_stage(sb + buf * STAGE, lane, wm, wn, acc);
        if (elect_one()) mbar_arrive(sb + SM_CONS + buf * 8);
        if (t < 5 && prod) {
            mbar_wait(sb + SM_CONS + buf * 8, par);
            int tn = t + 3;
            int phx = tn >> 2;
            issue_stage(sb + buf * STAGE, sb + SM_FULL + buf * 8,
                        phx ? dnp : upp, g_W4,
                        phx ? arow_dn : arow_up, n0, tn & 3);
        }
        if (++buf == NSTAGE) { buf = 0; par ^= 1; }
    }
    mbar_wait(sb + SM_EXTF, 0);
    compute_ext(sb, lane, wm, wn, acc);

    // epilogue: relu(acc) -> fp32 out (linear layout)
#pragma unroll
    for (int mt = 0; mt < 2; mt++) {
#pragma unroll
        for (int h = 0; h < 2; h++) {
            int m = m0 + wm * 32 + mt * 16 + (lane >> 2) + h * 8;
            float* orow = out + (size_t)m * DDIM;
#pragma unroll
            for (int nt = 0; nt < 8; nt++) {
                int n = n0 + wn * 64 + nt * 8 + (lane & 3) * 2;
                float2 o = make_float2(fmaxf(acc[mt][nt][2 * h],     0.0f),
                                       fmaxf(acc[mt][nt][2 * h + 1], 0.0f));
                *reinterpret_cast<float2*>(orow + n) = o;
            }
        }
    }
}

// ---------------------------------------------------------------------------
extern "C" void kernel_launch(void* const* d_in, const int* in_sizes, int n_in,
                              void* d_out, int out_size) {
    const float* x  = (const float*)d_in[0];
    const float* W1 = (const float*)d_in[1];
    const float* b1 = (const float*)d_in[2];
    const float* W2 = (const float*)d_in[3];
    const float* b2 = (const float*)d_in[4];
    const float* W3 = (const float*)d_in[5];
    const float* b3 = (const float*)d_in[6];
    const float* W4 = (const float*)d_in[7];
    const float* b4 = (const float*)d_in[8];
    float* out = (float*)d_out;

    cudaFuncSetAttribute(dp_iter_kernel, cudaFuncAttributeMaxDynamicSharedMemorySize, SMEM_BYTES);
    cudaFuncSetAttribute(final_kernel,   cudaFuncAttributeMaxDynamicSharedMemorySize, SMEM_BYTES);

    int total = MTOT * DDIM;
    prep_kernel<<<(total + 255) / 256, 256>>>(x, W1, b1, b2);
    xext_kernel<<<(MTOT + 255) / 256, 256>>>(x);
    split_w_kernel<<<(DDIM * DDIM + 255) / 256, 256>>>(W2, W4, W1, b1, b2, W3, b3, b4);

    int src = 0;
    for (int t = 0; t < 7; t++) {
        dp_iter_kernel<<<dim3(MTOT / BM, 2, 2), NTHR, SMEM_BYTES>>>(src);
        src ^= 1;
    }
    final_kernel<<<dim3(MTOT / BM, 2), NTHR, SMEM_BYTES>>>(out, src);
}